// round 14
// baseline (speedup 1.0000x reference)
#include <cuda_runtime.h>
#include <cuda_bf16.h>
#include <math.h>
#include <stdint.h>

// ---------------------------------------------------------------------------
// Problem constants (MLA prefill)
// ---------------------------------------------------------------------------
namespace {
constexpr int B_   = 2;
constexpr int S_   = 2048;
constexpr int H_   = 2048;
constexpr int NH_  = 16;
constexpr int QL   = 1536;
constexpr int KVL  = 512;
constexpr int DN   = 128;
constexpr int DR   = 64;
constexpr int DV   = 128;
constexpr int DQK  = 192;
constexpr int BS   = B_ * S_;
constexpr float SCALE = 0.07216878364870322f; // 1/sqrt(192)

constexpr int SM_QH  = 0;
constexpr int SM_QL  = SM_QH + 128 * 400;
constexpr int SM_KH  = SM_QL + 128 * 400;
constexpr int SM_KL  = SM_KH + 64 * 400;
constexpr int SM_VH  = SM_KL + 64 * 400;
constexpr int SM_VL  = SM_VH + 128 * 144;
constexpr int FLASH_SMEM = SM_VL + 128 * 144; // 190,464 B

// GEMM stage layout (bytes within one stage)
constexpr uint32_t G_AH = 0;       // 128 x 64B
constexpr uint32_t G_AL = 8192;    // 128 x 64B
constexpr uint32_t G_BH = 16384;   //  64 x 64B
constexpr uint32_t G_BL = 20480;   //  64 x 64B
constexpr uint32_t G_STG = 24576;  // 24 KB per stage, 2 stages = 48 KB
} // namespace

// ---------------------------------------------------------------------------
// Scratch (static device globals; no runtime allocation allowed)
// ---------------------------------------------------------------------------
__device__ float g_qlora[(size_t)BS * QL];
__device__ float g_kv[(size_t)BS * (KVL + DR)];   // only cols [0,512) valid
__device__ __nv_bfloat16 g_a3[(size_t)BS * 6144];    // activations [hi | lo]
__device__ __nv_bfloat16 g_b3[(size_t)3072 * 4608];  // weights     [hi | lo]
__device__ __nv_bfloat16 g_qh[(size_t)BS * NH_ * DQK];
__device__ __nv_bfloat16 g_ql2[(size_t)BS * NH_ * DQK];
__device__ __nv_bfloat16 g_kh[(size_t)BS * NH_ * DQK];
__device__ __nv_bfloat16 g_kl[(size_t)BS * NH_ * DQK];
__device__ __nv_bfloat16 g_vrh[(size_t)BS * NH_ * DV];       // V row-major hi
__device__ __nv_bfloat16 g_vrl[(size_t)BS * NH_ * DV];       // V row-major lo
__device__ __nv_bfloat16 g_vth[(size_t)B_ * NH_ * DV * S_];  // [b][h][dv][s]
__device__ __nv_bfloat16 g_vtl[(size_t)B_ * NH_ * DV * S_];
__device__ float g_freq[32];

// ---------------------------------------------------------------------------
// Helpers
// ---------------------------------------------------------------------------
__device__ __forceinline__ uint32_t smem_u32(const void* p) {
    uint32_t a;
    asm("{ .reg .u64 t; cvta.to.shared.u64 t, %1; cvt.u32.u64 %0, t; }" : "=r"(a) : "l"(p));
    return a;
}
__device__ __forceinline__ void cp_async16(uint32_t dst, const void* src) {
    asm volatile("cp.async.cg.shared.global [%0], [%1], 16;" :: "r"(dst), "l"(src) : "memory");
}
#define CP_COMMIT() asm volatile("cp.async.commit_group;" ::: "memory")
#define CP_WAIT1()  asm volatile("cp.async.wait_group 1;" ::: "memory")
#define CP_WAIT0()  asm volatile("cp.async.wait_group 0;" ::: "memory")

__device__ __forceinline__ void ldsm_x4(uint32_t& r0, uint32_t& r1, uint32_t& r2, uint32_t& r3,
                                        uint32_t addr) {
    asm volatile("ldmatrix.sync.aligned.m8n8.x4.shared.b16 {%0,%1,%2,%3}, [%4];"
                 : "=r"(r0), "=r"(r1), "=r"(r2), "=r"(r3) : "r"(addr));
}
__device__ __forceinline__ void mma_bf16(float* c, const uint32_t* a, const uint32_t* b) {
    asm volatile("mma.sync.aligned.m16n8k16.row.col.f32.bf16.bf16.f32 "
                 "{%0,%1,%2,%3}, {%4,%5,%6,%7}, {%8,%9}, {%0,%1,%2,%3};"
                 : "+f"(c[0]), "+f"(c[1]), "+f"(c[2]), "+f"(c[3])
                 : "r"(a[0]), "r"(a[1]), "r"(a[2]), "r"(a[3]), "r"(b[0]), "r"(b[1]));
}
__device__ __forceinline__ uint32_t swoff(int r, int c) {
    return (uint32_t)(r * 64 + ((c ^ ((r >> 1) & 3)) << 4));
}
__device__ __forceinline__ uint32_t pack_bf2(float x, float y) {
    __nv_bfloat162 t(__float2bfloat16(x), __float2bfloat16(y));
    return *(uint32_t*)&t;
}
__device__ __forceinline__ void hl_split2(float v0, float v1,
                                          __nv_bfloat162& hi, __nv_bfloat162& lo) {
    __nv_bfloat16 h0 = __float2bfloat16(v0), h1 = __float2bfloat16(v1);
    hi = __nv_bfloat162(h0, h1);
    lo = __nv_bfloat162(__float2bfloat16(v0 - __bfloat162float(h0)),
                        __float2bfloat16(v1 - __bfloat162float(h1)));
}

// ---------------------------------------------------------------------------
// hi/lo split conversion (plain)
// ---------------------------------------------------------------------------
__global__ void conv_hl_kernel(const float* __restrict__ in,
                               __nv_bfloat16* __restrict__ hi_o,
                               __nv_bfloat16* __restrict__ lo_o,
                               int R, int Rpad, int Kin, int ldin)
{
    const int kq = Kin >> 2;
    const int idx = blockIdx.x * blockDim.x + threadIdx.x;
    if (idx >= Rpad * kq) return;
    const int row = idx / kq, cg = idx - row * kq;
    float4 v = make_float4(0.f, 0.f, 0.f, 0.f);
    if (row < R) v = *(const float4*)(in + (size_t)row * ldin + cg * 4);
    __nv_bfloat162 hiA, loA, hiB, loB;
    hl_split2(v.x, v.y, hiA, loA);
    hl_split2(v.z, v.w, hiB, loB);
    const size_t o = (size_t)row * Kin + cg * 4;
    *(__nv_bfloat162*)(hi_o + o + 0) = hiA;
    *(__nv_bfloat162*)(hi_o + o + 2) = hiB;
    *(__nv_bfloat162*)(lo_o + o + 0) = loA;
    *(__nv_bfloat162*)(lo_o + o + 2) = loB;
}

// ---------------------------------------------------------------------------
// Fused RMSNorm + hi/lo split
// ---------------------------------------------------------------------------
__global__ __launch_bounds__(256)
void rms_conv_hl_kernel(const float* __restrict__ x, const float* __restrict__ w,
                        __nv_bfloat16* __restrict__ hi_o, __nv_bfloat16* __restrict__ lo_o,
                        int n, int ld)
{
    const int row = blockIdx.x;
    const float* p = x + (size_t)row * ld;
    float ss = 0.f;
    for (int i = threadIdx.x; i < n; i += 256) { float v = p[i]; ss = fmaf(v, v, ss); }
    __shared__ float red[8];
    #pragma unroll
    for (int o = 16; o > 0; o >>= 1) ss += __shfl_xor_sync(0xffffffffu, ss, o);
    if ((threadIdx.x & 31) == 0) red[threadIdx.x >> 5] = ss;
    __syncthreads();
    __shared__ float s_inv;
    if (threadIdx.x == 0) {
        float t = 0.f;
        #pragma unroll
        for (int i = 0; i < 8; i++) t += red[i];
        s_inv = rsqrtf(t / (float)n + 1e-6f);
    }
    __syncthreads();
    const float inv = s_inv;
    for (int i = threadIdx.x * 2; i < n; i += 512) {
        const float v0 = w[i] * p[i] * inv;
        const float v1 = w[i + 1] * p[i + 1] * inv;
        __nv_bfloat162 hi, lo;
        hl_split2(v0, v1, hi, lo);
        *(__nv_bfloat162*)(hi_o + (size_t)row * n + i) = hi;
        *(__nv_bfloat162*)(lo_o + (size_t)row * n + i) = lo;
    }
}

// ---------------------------------------------------------------------------
// HMMA bf16 GEMM, split-2 operands, fused segments; MODE templated so each
// instantiation compiles ONLY its epilogue (R13's runtime dispatch regressed).
//  0: fp32 C
//  1: q-proj: rope(d>=128 per 192-head) + hi/lo bf16 -> Chi/Clo
//  2: kvx:    col=h*256+d; d<128 -> kh/kl [row][h][192]; d>=128 -> Vh/Vl row-major
//  3: kv:     col<512 -> fp32 C; col in [512,576): rope + broadcast pe hi/lo
// ---------------------------------------------------------------------------
template <int MODE>
__global__ __launch_bounds__(128, 4)
void gemm_bf16_kernel(const __nv_bfloat16* __restrict__ Ah_g,
                      const __nv_bfloat16* __restrict__ Al_g,
                      const __nv_bfloat16* __restrict__ Bh_g,
                      const __nv_bfloat16* __restrict__ Bl_g,
                      float* __restrict__ C,
                      __nv_bfloat16* __restrict__ Chi, __nv_bfloat16* __restrict__ Clo,
                      __nv_bfloat16* __restrict__ Vh, __nv_bfloat16* __restrict__ Vl,
                      int N, int K, int ldc)
{
    __shared__ __nv_bfloat16 smv[2][G_STG / 2]; // 48 KB total
    const int tid = threadIdx.x;
    const int warp = tid >> 5, lane = tid & 31;
    const int m0 = blockIdx.y * 128, n0 = blockIdx.x * 64;
    const int KC = K / 32;

    const uint32_t sbase = smem_u32(&smv[0][0]);

    const int lr0 = tid >> 2, lc0 = tid & 3;
    const uint32_t so0 = swoff(lr0, lc0);

    const __nv_bfloat16* pAh = Ah_g + (size_t)(m0 + lr0) * K + lc0 * 8;
    const __nv_bfloat16* pAl = Al_g + (size_t)(m0 + lr0) * K + lc0 * 8;
    const __nv_bfloat16* pBh = Bh_g + (size_t)(n0 + lr0) * K + lc0 * 8;
    const __nv_bfloat16* pBl = Bl_g + (size_t)(n0 + lr0) * K + lc0 * 8;
    const size_t row32 = (size_t)32 * K;

    auto load_stage = [&](int s) {
        const uint32_t sb = sbase + s * G_STG;
        #pragma unroll
        for (int r = 0; r < 4; r++) {
            cp_async16(sb + G_AH + so0 + r * 2048, pAh + r * row32);
            cp_async16(sb + G_AL + so0 + r * 2048, pAl + r * row32);
        }
        #pragma unroll
        for (int r = 0; r < 2; r++) {
            cp_async16(sb + G_BH + so0 + r * 2048, pBh + r * row32);
            cp_async16(sb + G_BL + so0 + r * 2048, pBl + r * row32);
        }
        pAh += 32; pAl += 32; pBh += 32; pBl += 32;
    };

    const int wm = (warp >> 1) * 64, wn = (warp & 1) * 32;
    const int rA = wm + (lane & 15), cA = lane >> 4;
    const int swzA = (rA >> 1) & 3;
    const int rB = wn + (lane & 7) + ((lane >> 4) << 3), cB = (lane >> 3) & 1;
    const int swzB = (rB >> 1) & 3;

    float acc[4][4][4];
    #pragma unroll
    for (int i = 0; i < 4; i++)
        #pragma unroll
        for (int j = 0; j < 4; j++)
            #pragma unroll
            for (int k = 0; k < 4; k++) acc[i][j][k] = 0.f;

    load_stage(0); CP_COMMIT();
    load_stage(1); CP_COMMIT();
    CP_WAIT1();
    __syncthreads();

    for (int kc = 0; kc < KC; kc++) {
        const uint32_t sb = sbase + (kc & 1) * G_STG;
        #pragma unroll
        for (int h = 0; h < 2; h++) {
            const uint32_t aoff = (uint32_t)rA * 64 + (uint32_t)(((h * 2 + cA) ^ swzA) << 4);
            const uint32_t boff = (uint32_t)rB * 64 + (uint32_t)(((h * 2 + cB) ^ swzB) << 4);
            uint32_t ah[4][4], al[4][4], bh[4][2], bl[4][2];
            #pragma unroll
            for (int i = 0; i < 4; i++) {
                ldsm_x4(ah[i][0], ah[i][1], ah[i][2], ah[i][3],
                        sb + G_AH + aoff + (uint32_t)(16 * i) * 64);
                ldsm_x4(al[i][0], al[i][1], al[i][2], al[i][3],
                        sb + G_AL + aoff + (uint32_t)(16 * i) * 64);
            }
            #pragma unroll
            for (int j = 0; j < 2; j++) {
                uint32_t r0, r1, r2, r3;
                ldsm_x4(r0, r1, r2, r3, sb + G_BH + boff + (uint32_t)(16 * j) * 64);
                bh[2 * j][0] = r0; bh[2 * j][1] = r1;
                bh[2 * j + 1][0] = r2; bh[2 * j + 1][1] = r3;
                ldsm_x4(r0, r1, r2, r3, sb + G_BL + boff + (uint32_t)(16 * j) * 64);
                bl[2 * j][0] = r0; bl[2 * j][1] = r1;
                bl[2 * j + 1][0] = r2; bl[2 * j + 1][1] = r3;
            }
            #pragma unroll
            for (int i = 0; i < 4; i++)
                #pragma unroll
                for (int t = 0; t < 4; t++) {
                    mma_bf16(acc[i][t], ah[i], bh[t]);
                    mma_bf16(acc[i][t], al[i], bh[t]);
                    mma_bf16(acc[i][t], ah[i], bl[t]);
                }
        }
        __syncthreads();
        if (kc + 2 < KC) load_stage(kc & 1);
        CP_COMMIT();
        if (kc + 1 < KC) { CP_WAIT1(); __syncthreads(); }
    }

    const int gr = lane >> 2, gc = (lane & 3) * 2;
    #pragma unroll
    for (int i = 0; i < 4; i++) {
        const int row0 = m0 + wm + i * 16 + gr;
        #pragma unroll
        for (int t = 0; t < 4; t++) {
            const int col = n0 + wn + t * 8 + gc;
            #pragma unroll
            for (int rr = 0; rr < 2; rr++) {
                const int row = row0 + rr * 8;
                float v0 = acc[i][t][rr * 2 + 0];
                float v1 = acc[i][t][rr * 2 + 1];
                if constexpr (MODE == 0) {
                    if (rr == 0 ? (col < N) : (col < N))
                        *(float2*)(C + (size_t)row * ldc + col) = make_float2(v0, v1);
                } else if constexpr (MODE == 1) {
                    const int d = col % DQK;
                    if (d >= DN) {
                        const int fi = (d - DN) >> 1;
                        const float f = (float)(row & (S_ - 1)) * g_freq[fi];
                        float sn, cs;
                        sincosf(f, &sn, &cs);
                        const float e = v0, o = v1;
                        v0 = e * cs - o * sn;
                        v1 = e * sn + o * cs;
                    }
                    __nv_bfloat162 hi, lo;
                    hl_split2(v0, v1, hi, lo);
                    *(__nv_bfloat162*)(Chi + (size_t)row * ldc + col) = hi;
                    *(__nv_bfloat162*)(Clo + (size_t)row * ldc + col) = lo;
                } else if constexpr (MODE == 2) {
                    const int hh = col >> 8, d = col & 255;
                    __nv_bfloat162 hi, lo;
                    hl_split2(v0, v1, hi, lo);
                    if (d < DN) {
                        const size_t o = ((size_t)row * NH_ + hh) * DQK + d;
                        *(__nv_bfloat162*)(Chi + o) = hi;
                        *(__nv_bfloat162*)(Clo + o) = lo;
                    } else {
                        const size_t o = (size_t)row * (NH_ * DV) + hh * DV + (d - DN);
                        *(__nv_bfloat162*)(Vh + o) = hi;
                        *(__nv_bfloat162*)(Vl + o) = lo;
                    }
                } else { // MODE == 3
                    if (col < KVL) {
                        *(float2*)(C + (size_t)row * ldc + col) = make_float2(v0, v1);
                    } else if (col < KVL + DR) {
                        const int fi = (col - KVL) >> 1;
                        const float f = (float)(row & (S_ - 1)) * g_freq[fi];
                        float sn, cs;
                        sincosf(f, &sn, &cs);
                        const float e = v0, o = v1;
                        v0 = e * cs - o * sn;
                        v1 = e * sn + o * cs;
                        __nv_bfloat162 hi, lo;
                        hl_split2(v0, v1, hi, lo);
                        const size_t base = (size_t)row * NH_ * DQK + DN + (col - KVL);
                        #pragma unroll
                        for (int h16 = 0; h16 < NH_; h16++) {
                            *(__nv_bfloat162*)(Chi + base + (size_t)h16 * DQK) = hi;
                            *(__nv_bfloat162*)(Clo + base + (size_t)h16 * DQK) = lo;
                        }
                    }
                }
            }
        }
    }
}

// ---------------------------------------------------------------------------
// freq init
// ---------------------------------------------------------------------------
__global__ void freq_init_kernel()
{
    if (threadIdx.x < 32)
        g_freq[threadIdx.x] = (float)pow(10000.0, -(double)threadIdx.x / 32.0);
}

// ---------------------------------------------------------------------------
// V transpose (bf16 hi/lo): vr [row][h][128] -> vt [b][h][dv][s]
// ---------------------------------------------------------------------------
__global__ void convvt2_kernel(const __nv_bfloat16* __restrict__ vrh,
                               const __nv_bfloat16* __restrict__ vrl,
                               __nv_bfloat16* __restrict__ vth,
                               __nv_bfloat16* __restrict__ vtl)
{
    __shared__ __nv_bfloat16 th[32][33], tl[32][33];
    const int bh = blockIdx.z;
    const int b = bh >> 4, h = bh & 15;
    const int s0 = blockIdx.x * 32, dv0 = blockIdx.y * 32;
    const int tx = threadIdx.x, ty = threadIdx.y;
    #pragma unroll
    for (int j = 0; j < 4; j++) {
        const int s = s0 + ty + 8 * j;
        const size_t o = (size_t)(b * S_ + s) * (NH_ * DV) + h * DV + dv0 + tx;
        th[ty + 8 * j][tx] = vrh[o];
        tl[ty + 8 * j][tx] = vrl[o];
    }
    __syncthreads();
    #pragma unroll
    for (int j = 0; j < 4; j++) {
        const int dv = dv0 + ty + 8 * j;
        const size_t o = ((size_t)bh * DV + dv) * S_ + s0 + tx;
        vth[o] = th[tx][ty + 8 * j];
        vtl[o] = tl[tx][ty + 8 * j];
    }
}

// ---------------------------------------------------------------------------
// Flash attention on HMMA (R11/R12 proven) — unchanged
// ---------------------------------------------------------------------------
__global__ __launch_bounds__(256, 1)
void flash_mma_kernel(const __nv_bfloat16* __restrict__ qh, const __nv_bfloat16* __restrict__ ql,
                      const __nv_bfloat16* __restrict__ kh, const __nv_bfloat16* __restrict__ kl,
                      const __nv_bfloat16* __restrict__ vth, const __nv_bfloat16* __restrict__ vtl,
                      __nv_bfloat16* __restrict__ ohi, __nv_bfloat16* __restrict__ olo)
{
    extern __shared__ __align__(128) char sm[];
    const uint32_t sb = smem_u32(sm);
    const int tid = threadIdx.x, warp = tid >> 5, lane = tid & 31;
    const int h = blockIdx.y, b = blockIdx.z;
    const int q0 = blockIdx.x * 128;
    const int wr = warp * 16;

    auto load_k = [&](int kt) {
        for (int u = tid; u < 64 * 24; u += 256) {
            const int r = u / 24, c = u % 24;
            const size_t off = ((size_t)(b * S_ + kt + r) * NH_ + h) * 192 + c * 8;
            cp_async16(sb + SM_KH + r * 400 + c * 16, kh + off);
            cp_async16(sb + SM_KL + r * 400 + c * 16, kl + off);
        }
    };
    auto load_v = [&](int kt) {
        for (int u = tid; u < 128 * 8; u += 256) {
            const int dv = u / 8, ck = u % 8;
            const size_t off = ((size_t)(b * NH_ + h) * DV + dv) * S_ + kt + ck * 8;
            cp_async16(sb + SM_VH + dv * 144 + ck * 16, vth + off);
            cp_async16(sb + SM_VL + dv * 144 + ck * 16, vtl + off);
        }
    };

    for (int u = tid; u < 128 * 24; u += 256) {
        const int r = u / 24, c = u % 24;
        const size_t off = ((size_t)(b * S_ + q0 + r) * NH_ + h) * 192 + c * 8;
        cp_async16(sb + SM_QH + r * 400 + c * 16, qh + off);
        cp_async16(sb + SM_QL + r * 400 + c * 16, ql + off);
    }
    load_k(0);
    CP_COMMIT();
    load_v(0);
    CP_COMMIT();

    float oacc[16][4];
    #pragma unroll
    for (int i = 0; i < 16; i++)
        #pragma unroll
        for (int j = 0; j < 4; j++) oacc[i][j] = 0.f;
    float m0 = -1e30f, m1 = -1e30f, l0 = 0.f, l1 = 0.f;

    const uint32_t aQoff = (uint32_t)(wr + (lane & 15)) * 400 + ((lane >> 4) << 4);
    const int rB8  = (lane & 7) + ((lane >> 4) << 3);
    const uint32_t bKoff = (uint32_t)rB8 * 400 + (((lane >> 3) & 1) << 4);
    const uint32_t bVoff = (uint32_t)rB8 * 144 + (((lane >> 3) & 1) << 4);

    for (int kt = 0; kt < S_; kt += 64) {
        const bool has_next = (kt + 64 < S_);
        CP_WAIT1();
        __syncthreads();

        float sacc[8][4];
        #pragma unroll
        for (int i = 0; i < 8; i++)
            #pragma unroll
            for (int j = 0; j < 4; j++) sacc[i][j] = 0.f;

        #pragma unroll
        for (int ks = 0; ks < 12; ks++) {
            uint32_t ah[4], al[4];
            ldsm_x4(ah[0], ah[1], ah[2], ah[3], sb + SM_QH + aQoff + ks * 32);
            ldsm_x4(al[0], al[1], al[2], al[3], sb + SM_QL + aQoff + ks * 32);
            #pragma unroll
            for (int g = 0; g < 4; g++) {
                uint32_t h0, h1, h2, h3, l0r, l1r, l2r, l3r;
                ldsm_x4(h0, h1, h2, h3,
                        sb + SM_KH + bKoff + (uint32_t)g * 16 * 400 + ks * 32);
                ldsm_x4(l0r, l1r, l2r, l3r,
                        sb + SM_KL + bKoff + (uint32_t)g * 16 * 400 + ks * 32);
                uint32_t bh0[2] = {h0, h1}, bh1[2] = {h2, h3};
                uint32_t bl0[2] = {l0r, l1r}, bl1[2] = {l2r, l3r};
                mma_bf16(sacc[2 * g],     ah, bh0);
                mma_bf16(sacc[2 * g + 1], ah, bh1);
                mma_bf16(sacc[2 * g],     al, bh0);
                mma_bf16(sacc[2 * g + 1], al, bh1);
                mma_bf16(sacc[2 * g],     ah, bl0);
                mma_bf16(sacc[2 * g + 1], ah, bl1);
            }
        }

        __syncthreads();
        if (has_next) load_k(kt + 64);
        CP_COMMIT();

        float mx0 = -1e30f, mx1 = -1e30f;
        #pragma unroll
        for (int nt = 0; nt < 8; nt++) {
            #pragma unroll
            for (int j = 0; j < 4; j++) sacc[nt][j] *= SCALE;
            mx0 = fmaxf(mx0, fmaxf(sacc[nt][0], sacc[nt][1]));
            mx1 = fmaxf(mx1, fmaxf(sacc[nt][2], sacc[nt][3]));
        }
        mx0 = fmaxf(mx0, __shfl_xor_sync(0xffffffffu, mx0, 1));
        mx0 = fmaxf(mx0, __shfl_xor_sync(0xffffffffu, mx0, 2));
        mx1 = fmaxf(mx1, __shfl_xor_sync(0xffffffffu, mx1, 1));
        mx1 = fmaxf(mx1, __shfl_xor_sync(0xffffffffu, mx1, 2));
        const float mn0 = fmaxf(m0, mx0), mn1 = fmaxf(m1, mx1);
        const float al0 = __expf(m0 - mn0), al1 = __expf(m1 - mn1);
        float rs0 = 0.f, rs1 = 0.f;
        #pragma unroll
        for (int nt = 0; nt < 8; nt++) {
            sacc[nt][0] = __expf(sacc[nt][0] - mn0);
            sacc[nt][1] = __expf(sacc[nt][1] - mn0);
            sacc[nt][2] = __expf(sacc[nt][2] - mn1);
            sacc[nt][3] = __expf(sacc[nt][3] - mn1);
            rs0 += sacc[nt][0] + sacc[nt][1];
            rs1 += sacc[nt][2] + sacc[nt][3];
        }
        rs0 += __shfl_xor_sync(0xffffffffu, rs0, 1);
        rs0 += __shfl_xor_sync(0xffffffffu, rs0, 2);
        rs1 += __shfl_xor_sync(0xffffffffu, rs1, 1);
        rs1 += __shfl_xor_sync(0xffffffffu, rs1, 2);
        l0 = l0 * al0 + rs0; m0 = mn0;
        l1 = l1 * al1 + rs1; m1 = mn1;
        #pragma unroll
        for (int nt = 0; nt < 16; nt++) {
            oacc[nt][0] *= al0; oacc[nt][1] *= al0;
            oacc[nt][2] *= al1; oacc[nt][3] *= al1;
        }

        if (has_next) { CP_WAIT1(); } else { CP_WAIT0(); }
        __syncthreads();

        #pragma unroll
        for (int kk = 0; kk < 4; kk++) {
            uint32_t ah[4], alr[4];
            {
                const float* p0 = sacc[2 * kk];
                const float* p1 = sacc[2 * kk + 1];
                float h00 = __bfloat162float(__float2bfloat16(p0[0]));
                float h01 = __bfloat162float(__float2bfloat16(p0[1]));
                float h02 = __bfloat162float(__float2bfloat16(p0[2]));
                float h03 = __bfloat162float(__float2bfloat16(p0[3]));
                float h10 = __bfloat162float(__float2bfloat16(p1[0]));
                float h11 = __bfloat162float(__float2bfloat16(p1[1]));
                float h12 = __bfloat162float(__float2bfloat16(p1[2]));
                float h13 = __bfloat162float(__float2bfloat16(p1[3]));
                ah[0] = pack_bf2(p0[0], p0[1]);
                ah[1] = pack_bf2(p0[2], p0[3]);
                ah[2] = pack_bf2(p1[0], p1[1]);
                ah[3] = pack_bf2(p1[2], p1[3]);
                alr[0] = pack_bf2(p0[0] - h00, p0[1] - h01);
                alr[1] = pack_bf2(p0[2] - h02, p0[3] - h03);
                alr[2] = pack_bf2(p1[0] - h10, p1[1] - h11);
                alr[3] = pack_bf2(p1[2] - h12, p1[3] - h13);
            }
            #pragma unroll
            for (int half = 0; half < 2; half++) {
                uint32_t bv[8][2];
                #pragma unroll
                for (int g = 0; g < 4; g++) {
                    uint32_t r0, r1, r2, r3;
                    ldsm_x4(r0, r1, r2, r3,
                            sb + SM_VH + bVoff + (uint32_t)(half * 64 + g * 16) * 144 + kk * 32);
                    bv[2 * g][0] = r0; bv[2 * g][1] = r1;
                    bv[2 * g + 1][0] = r2; bv[2 * g + 1][1] = r3;
                }
                #pragma unroll
                for (int t = 0; t < 8; t++) {
                    mma_bf16(oacc[half * 8 + t], ah, bv[t]);
                    mma_bf16(oacc[half * 8 + t], alr, bv[t]);
                }
                #pragma unroll
                for (int g = 0; g < 4; g++) {
                    uint32_t r0, r1, r2, r3;
                    ldsm_x4(r0, r1, r2, r3,
                            sb + SM_VL + bVoff + (uint32_t)(half * 64 + g * 16) * 144 + kk * 32);
                    bv[2 * g][0] = r0; bv[2 * g][1] = r1;
                    bv[2 * g + 1][0] = r2; bv[2 * g + 1][1] = r3;
                }
                #pragma unroll
                for (int t = 0; t < 8; t++)
                    mma_bf16(oacc[half * 8 + t], ah, bv[t]);
            }
        }

        __syncthreads();
        if (has_next) load_v(kt + 64);
        CP_COMMIT();
    }

    const float inv0 = 1.f / l0, inv1 = 1.f / l1;
    const int gr = lane >> 2, gc = (lane & 3) * 2;
    const int row0 = b * S_ + q0 + wr + gr;
    #pragma unroll
    for (int nt = 0; nt < 16; nt++) {
        const int col = h * DV + nt * 8 + gc;
        __nv_bfloat162 hi, lo;
        hl_split2(oacc[nt][0] * inv0, oacc[nt][1] * inv0, hi, lo);
        *(__nv_bfloat162*)(ohi + (size_t)row0 * (NH_ * DV) + col) = hi;
        *(__nv_bfloat162*)(olo + (size_t)row0 * (NH_ * DV) + col) = lo;
        hl_split2(oacc[nt][2] * inv1, oacc[nt][3] * inv1, hi, lo);
        *(__nv_bfloat162*)(ohi + (size_t)(row0 + 8) * (NH_ * DV) + col) = hi;
        *(__nv_bfloat162*)(olo + (size_t)(row0 + 8) * (NH_ * DV) + col) = lo;
    }
}

// ---------------------------------------------------------------------------
// Launcher
// ---------------------------------------------------------------------------
static inline void run_conv(const float* in, __nv_bfloat16* hi, __nv_bfloat16* lo,
                            int R, int Rpad, int Kin, int ldin)
{
    const int total = Rpad * (Kin / 4);
    conv_hl_kernel<<<(total + 255) / 256, 256>>>(in, hi, lo, R, Rpad, Kin, ldin);
}

extern "C" void kernel_launch(void* const* d_in, const int* in_sizes, int n_in,
                              void* d_out, int out_size)
{
    const float* hs    = (const float*)d_in[0];
    const float* wq_a  = (const float*)d_in[1];
    const float* qnw   = (const float*)d_in[2];
    const float* wq_b  = (const float*)d_in[3];
    const float* wkv_a = (const float*)d_in[4];
    const float* kvnw  = (const float*)d_in[5];
    const float* wkv_b = (const float*)d_in[6];
    const float* wo    = (const float*)d_in[7];
    float* out = (float*)d_out;

    void* p;
    cudaGetSymbolAddress(&p, g_qlora); float* qlora = (float*)p;
    cudaGetSymbolAddress(&p, g_kv);    float* kvbuf = (float*)p;
    cudaGetSymbolAddress(&p, g_a3);    __nv_bfloat16* a3 = (__nv_bfloat16*)p;
    cudaGetSymbolAddress(&p, g_b3);    __nv_bfloat16* b3 = (__nv_bfloat16*)p;
    cudaGetSymbolAddress(&p, g_qh);    __nv_bfloat16* qh = (__nv_bfloat16*)p;
    cudaGetSymbolAddress(&p, g_ql2);   __nv_bfloat16* ql = (__nv_bfloat16*)p;
    cudaGetSymbolAddress(&p, g_kh);    __nv_bfloat16* kh = (__nv_bfloat16*)p;
    cudaGetSymbolAddress(&p, g_kl);    __nv_bfloat16* kl = (__nv_bfloat16*)p;
    cudaGetSymbolAddress(&p, g_vrh);   __nv_bfloat16* vrh = (__nv_bfloat16*)p;
    cudaGetSymbolAddress(&p, g_vrl);   __nv_bfloat16* vrl = (__nv_bfloat16*)p;
    cudaGetSymbolAddress(&p, g_vth);   __nv_bfloat16* vth = (__nv_bfloat16*)p;
    cudaGetSymbolAddress(&p, g_vtl);   __nv_bfloat16* vtl = (__nv_bfloat16*)p;

    cudaFuncSetAttribute(flash_mma_kernel, cudaFuncAttributeMaxDynamicSharedMemorySize,
                         FLASH_SMEM);

    freq_init_kernel<<<1, 32>>>();

    // 1) q_lora = hs @ wq_a^T        [4096, 1536], K=2048
    run_conv(hs, a3, a3 + (size_t)BS * H_, BS, BS, H_, H_);
    run_conv(wq_a, b3, b3 + (size_t)QL * H_, QL, QL, H_, H_);
    gemm_bf16_kernel<0><<<dim3(QL / 64, BS / 128), 128>>>(
        a3, a3 + (size_t)BS * H_, b3, b3 + (size_t)QL * H_,
        qlora, nullptr, nullptr, nullptr, nullptr, QL, H_, QL);

    // 2) kv = hs @ wkv_a^T  [4096, 576] (Npad 640): fp32 kv_c + rope'd pe -> kh/kl (bcast)
    run_conv(wkv_a, b3, b3 + (size_t)640 * H_, KVL + DR, 640, H_, H_);
    gemm_bf16_kernel<3><<<dim3(640 / 64, BS / 128), 128>>>(
        a3, a3 + (size_t)BS * H_, b3, b3 + (size_t)640 * H_,
        kvbuf, kh, kl, nullptr, nullptr, KVL + DR, H_, KVL + DR);

    // 3) q = q_lora @ wq_b^T         [4096, 3072], K=1536; fused rope + hi/lo out
    rms_conv_hl_kernel<<<BS, 256>>>(qlora, qnw, a3, a3 + (size_t)BS * QL, QL, QL);
    run_conv(wq_b, b3, b3 + (size_t)3072 * QL, NH_ * DQK, NH_ * DQK, QL, QL);
    gemm_bf16_kernel<1><<<dim3((NH_ * DQK) / 64, BS / 128), 128>>>(
        a3, a3 + (size_t)BS * QL, b3, b3 + (size_t)3072 * QL,
        nullptr, qh, ql, nullptr, nullptr, NH_ * DQK, QL, NH_ * DQK);

    // 4) kv_x = kv_c @ wkv_b^T       [4096, 4096], K=512: direct kh/kl + vrh/vrl out
    rms_conv_hl_kernel<<<BS, 256>>>(kvbuf, kvnw, a3, a3 + (size_t)BS * KVL, KVL, KVL + DR);
    run_conv(wkv_b, b3, b3 + (size_t)4096 * KVL, NH_ * (DN + DV), NH_ * (DN + DV), KVL, KVL);
    gemm_bf16_kernel<2><<<dim3((NH_ * (DN + DV)) / 64, BS / 128), 128>>>(
        a3, a3 + (size_t)BS * KVL, b3, b3 + (size_t)4096 * KVL,
        nullptr, kh, kl, vrh, vrl, NH_ * (DN + DV), KVL, 0);

    // 5) V transpose (bf16 hi/lo)
    convvt2_kernel<<<dim3(S_ / 32, DV / 32, B_ * NH_), dim3(32, 8)>>>(vrh, vrl, vth, vtl);

    // 6) flash attention -> a3 hi/lo directly (split-2 A for final GEMM)
    flash_mma_kernel<<<dim3(S_ / 128, NH_, B_), 256, FLASH_SMEM>>>(
        qh, ql, kh, kl, vth, vtl, a3, a3 + (size_t)BS * (NH_ * DV));

    // 7) out = attn @ wo^T           [4096, 2048], K=2048
    run_conv(wo, b3, b3 + (size_t)H_ * (NH_ * DV), H_, H_, NH_ * DV, NH_ * DV);
    gemm_bf16_kernel<0><<<dim3(H_ / 64, BS / 128), 128>>>(
        a3, a3 + (size_t)BS * (NH_ * DV), b3, b3 + (size_t)H_ * (NH_ * DV),
        out, nullptr, nullptr, nullptr, nullptr, H_, NH_ * DV, H_);
}

// round 15
// speedup vs baseline: 1.0119x; 1.0119x over previous
#include <cuda_runtime.h>
#include <cuda_bf16.h>
#include <math.h>
#include <stdint.h>

// ---------------------------------------------------------------------------
// Problem constants (MLA prefill)
// ---------------------------------------------------------------------------
namespace {
constexpr int B_   = 2;
constexpr int S_   = 2048;
constexpr int H_   = 2048;
constexpr int NH_  = 16;
constexpr int QL   = 1536;
constexpr int KVL  = 512;
constexpr int DN   = 128;
constexpr int DR   = 64;
constexpr int DV   = 128;
constexpr int DQK  = 192;
constexpr int BS   = B_ * S_;
constexpr float SCALE = 0.07216878364870322f; // 1/sqrt(192)

constexpr int SM_QH  = 0;
constexpr int SM_QL  = SM_QH + 128 * 400;
constexpr int SM_KH  = SM_QL + 128 * 400;
constexpr int SM_KL  = SM_KH + 64 * 400;
constexpr int SM_VH  = SM_KL + 64 * 400;
constexpr int SM_VL  = SM_VH + 128 * 144;
constexpr int FLASH_SMEM = SM_VL + 128 * 144; // 190,464 B

// GEMM stage layout (bytes within one stage)
constexpr uint32_t G_AH = 0;       // 128 x 64B
constexpr uint32_t G_AL = 8192;    // 128 x 64B
constexpr uint32_t G_BH = 16384;   //  64 x 64B
constexpr uint32_t G_BL = 20480;   //  64 x 64B
constexpr uint32_t G_STG = 24576;  // 24 KB per stage, 2 stages = 48 KB
} // namespace

// ---------------------------------------------------------------------------
// Scratch (static device globals; no runtime allocation allowed)
// ---------------------------------------------------------------------------
__device__ float g_qlora[(size_t)BS * QL];
__device__ float g_kv[(size_t)BS * (KVL + DR)];   // only cols [0,512) valid
__device__ __nv_bfloat16 g_a3[(size_t)BS * 6144];    // activations [hi | lo]
__device__ __nv_bfloat16 g_b3[(size_t)3072 * 4608];  // weights     [hi | lo]
__device__ __nv_bfloat16 g_qh[(size_t)BS * NH_ * DQK];
__device__ __nv_bfloat16 g_ql2[(size_t)BS * NH_ * DQK];
__device__ __nv_bfloat16 g_kh[(size_t)BS * NH_ * DQK];
__device__ __nv_bfloat16 g_kl[(size_t)BS * NH_ * DQK];
__device__ __nv_bfloat16 g_vrh[(size_t)BS * NH_ * DV];       // V row-major hi
__device__ __nv_bfloat16 g_vrl[(size_t)BS * NH_ * DV];       // V row-major lo
__device__ __nv_bfloat16 g_vth[(size_t)B_ * NH_ * DV * S_];  // [b][h][dv][s]
__device__ __nv_bfloat16 g_vtl[(size_t)B_ * NH_ * DV * S_];
__device__ float g_freq[32];

// ---------------------------------------------------------------------------
// Helpers
// ---------------------------------------------------------------------------
__device__ __forceinline__ uint32_t smem_u32(const void* p) {
    uint32_t a;
    asm("{ .reg .u64 t; cvta.to.shared.u64 t, %1; cvt.u32.u64 %0, t; }" : "=r"(a) : "l"(p));
    return a;
}
__device__ __forceinline__ void cp_async16(uint32_t dst, const void* src) {
    asm volatile("cp.async.cg.shared.global [%0], [%1], 16;" :: "r"(dst), "l"(src) : "memory");
}
#define CP_COMMIT() asm volatile("cp.async.commit_group;" ::: "memory")
#define CP_WAIT1()  asm volatile("cp.async.wait_group 1;" ::: "memory")
#define CP_WAIT0()  asm volatile("cp.async.wait_group 0;" ::: "memory")

__device__ __forceinline__ void ldsm_x4(uint32_t& r0, uint32_t& r1, uint32_t& r2, uint32_t& r3,
                                        uint32_t addr) {
    asm volatile("ldmatrix.sync.aligned.m8n8.x4.shared.b16 {%0,%1,%2,%3}, [%4];"
                 : "=r"(r0), "=r"(r1), "=r"(r2), "=r"(r3) : "r"(addr));
}
__device__ __forceinline__ void mma_bf16(float* c, const uint32_t* a, const uint32_t* b) {
    asm volatile("mma.sync.aligned.m16n8k16.row.col.f32.bf16.bf16.f32 "
                 "{%0,%1,%2,%3}, {%4,%5,%6,%7}, {%8,%9}, {%0,%1,%2,%3};"
                 : "+f"(c[0]), "+f"(c[1]), "+f"(c[2]), "+f"(c[3])
                 : "r"(a[0]), "r"(a[1]), "r"(a[2]), "r"(a[3]), "r"(b[0]), "r"(b[1]));
}
__device__ __forceinline__ uint32_t swoff(int r, int c) {
    return (uint32_t)(r * 64 + ((c ^ ((r >> 1) & 3)) << 4));
}
__device__ __forceinline__ uint32_t pack_bf2(float x, float y) {
    __nv_bfloat162 t(__float2bfloat16(x), __float2bfloat16(y));
    return *(uint32_t*)&t;
}
__device__ __forceinline__ void hl_split2(float v0, float v1,
                                          __nv_bfloat162& hi, __nv_bfloat162& lo) {
    __nv_bfloat16 h0 = __float2bfloat16(v0), h1 = __float2bfloat16(v1);
    hi = __nv_bfloat162(h0, h1);
    lo = __nv_bfloat162(__float2bfloat16(v0 - __bfloat162float(h0)),
                        __float2bfloat16(v1 - __bfloat162float(h1)));
}

// ---------------------------------------------------------------------------
// hi/lo split conversion (plain)
// ---------------------------------------------------------------------------
__global__ void conv_hl_kernel(const float* __restrict__ in,
                               __nv_bfloat16* __restrict__ hi_o,
                               __nv_bfloat16* __restrict__ lo_o,
                               int R, int Rpad, int Kin, int ldin)
{
    const int kq = Kin >> 2;
    const int idx = blockIdx.x * blockDim.x + threadIdx.x;
    if (idx >= Rpad * kq) return;
    const int row = idx / kq, cg = idx - row * kq;
    float4 v = make_float4(0.f, 0.f, 0.f, 0.f);
    if (row < R) v = *(const float4*)(in + (size_t)row * ldin + cg * 4);
    __nv_bfloat162 hiA, loA, hiB, loB;
    hl_split2(v.x, v.y, hiA, loA);
    hl_split2(v.z, v.w, hiB, loB);
    const size_t o = (size_t)row * Kin + cg * 4;
    *(__nv_bfloat162*)(hi_o + o + 0) = hiA;
    *(__nv_bfloat162*)(hi_o + o + 2) = hiB;
    *(__nv_bfloat162*)(lo_o + o + 0) = loA;
    *(__nv_bfloat162*)(lo_o + o + 2) = loB;
}

// ---------------------------------------------------------------------------
// Fused RMSNorm + hi/lo split
// ---------------------------------------------------------------------------
__global__ __launch_bounds__(256)
void rms_conv_hl_kernel(const float* __restrict__ x, const float* __restrict__ w,
                        __nv_bfloat16* __restrict__ hi_o, __nv_bfloat16* __restrict__ lo_o,
                        int n, int ld)
{
    const int row = blockIdx.x;
    const float* p = x + (size_t)row * ld;
    float ss = 0.f;
    for (int i = threadIdx.x; i < n; i += 256) { float v = p[i]; ss = fmaf(v, v, ss); }
    __shared__ float red[8];
    #pragma unroll
    for (int o = 16; o > 0; o >>= 1) ss += __shfl_xor_sync(0xffffffffu, ss, o);
    if ((threadIdx.x & 31) == 0) red[threadIdx.x >> 5] = ss;
    __syncthreads();
    __shared__ float s_inv;
    if (threadIdx.x == 0) {
        float t = 0.f;
        #pragma unroll
        for (int i = 0; i < 8; i++) t += red[i];
        s_inv = rsqrtf(t / (float)n + 1e-6f);
    }
    __syncthreads();
    const float inv = s_inv;
    for (int i = threadIdx.x * 2; i < n; i += 512) {
        const float v0 = w[i] * p[i] * inv;
        const float v1 = w[i + 1] * p[i + 1] * inv;
        __nv_bfloat162 hi, lo;
        hl_split2(v0, v1, hi, lo);
        *(__nv_bfloat162*)(hi_o + (size_t)row * n + i) = hi;
        *(__nv_bfloat162*)(lo_o + (size_t)row * n + i) = lo;
    }
}

// ===========================================================================
// GEMM mainloop body (shared text; each kernel below is a full copy so the
// mode-0/1 kernel keeps R12's exact codegen).
// ===========================================================================
#define GEMM_MAINLOOP_BODY                                                        \
    __shared__ __nv_bfloat16 smv[2][G_STG / 2];                                   \
    const int tid = threadIdx.x;                                                  \
    const int warp = tid >> 5, lane = tid & 31;                                   \
    const int m0 = blockIdx.y * 128, n0 = blockIdx.x * 64;                        \
    const int KC = K / 32;                                                        \
    const uint32_t sbase = smem_u32(&smv[0][0]);                                  \
    const int lr0 = tid >> 2, lc0 = tid & 3;                                      \
    const uint32_t so0 = swoff(lr0, lc0);                                         \
    const __nv_bfloat16* pAh = Ah_g + (size_t)(m0 + lr0) * K + lc0 * 8;           \
    const __nv_bfloat16* pAl = Al_g + (size_t)(m0 + lr0) * K + lc0 * 8;           \
    const __nv_bfloat16* pBh = Bh_g + (size_t)(n0 + lr0) * K + lc0 * 8;           \
    const __nv_bfloat16* pBl = Bl_g + (size_t)(n0 + lr0) * K + lc0 * 8;           \
    const size_t row32 = (size_t)32 * K;                                          \
    auto load_stage = [&](int s) {                                                \
        const uint32_t sb = sbase + s * G_STG;                                    \
        _Pragma("unroll")                                                         \
        for (int r = 0; r < 4; r++) {                                             \
            cp_async16(sb + G_AH + so0 + r * 2048, pAh + r * row32);              \
            cp_async16(sb + G_AL + so0 + r * 2048, pAl + r * row32);              \
        }                                                                         \
        _Pragma("unroll")                                                         \
        for (int r = 0; r < 2; r++) {                                             \
            cp_async16(sb + G_BH + so0 + r * 2048, pBh + r * row32);              \
            cp_async16(sb + G_BL + so0 + r * 2048, pBl + r * row32);              \
        }                                                                         \
        pAh += 32; pAl += 32; pBh += 32; pBl += 32;                               \
    };                                                                            \
    const int wm = (warp >> 1) * 64, wn = (warp & 1) * 32;                        \
    const int rA = wm + (lane & 15), cA = lane >> 4;                              \
    const int swzA = (rA >> 1) & 3;                                               \
    const int rB = wn + (lane & 7) + ((lane >> 4) << 3), cB = (lane >> 3) & 1;    \
    const int swzB = (rB >> 1) & 3;                                               \
    float acc[4][4][4];                                                           \
    _Pragma("unroll")                                                             \
    for (int i = 0; i < 4; i++)                                                   \
        _Pragma("unroll")                                                         \
        for (int j = 0; j < 4; j++)                                               \
            _Pragma("unroll")                                                     \
            for (int k = 0; k < 4; k++) acc[i][j][k] = 0.f;                       \
    load_stage(0); CP_COMMIT();                                                   \
    load_stage(1); CP_COMMIT();                                                   \
    CP_WAIT1();                                                                   \
    __syncthreads();                                                              \
    for (int kc = 0; kc < KC; kc++) {                                             \
        const uint32_t sb = sbase + (kc & 1) * G_STG;                             \
        _Pragma("unroll")                                                         \
        for (int h = 0; h < 2; h++) {                                             \
            const uint32_t aoff = (uint32_t)rA * 64 +                             \
                                  (uint32_t)(((h * 2 + cA) ^ swzA) << 4);         \
            const uint32_t boff = (uint32_t)rB * 64 +                             \
                                  (uint32_t)(((h * 2 + cB) ^ swzB) << 4);         \
            uint32_t ah[4][4], al[4][4], bh[4][2], bl[4][2];                      \
            _Pragma("unroll")                                                     \
            for (int i = 0; i < 4; i++) {                                         \
                ldsm_x4(ah[i][0], ah[i][1], ah[i][2], ah[i][3],                   \
                        sb + G_AH + aoff + (uint32_t)(16 * i) * 64);              \
                ldsm_x4(al[i][0], al[i][1], al[i][2], al[i][3],                   \
                        sb + G_AL + aoff + (uint32_t)(16 * i) * 64);              \
            }                                                                     \
            _Pragma("unroll")                                                     \
            for (int j = 0; j < 2; j++) {                                         \
                uint32_t r0, r1, r2, r3;                                          \
                ldsm_x4(r0, r1, r2, r3, sb + G_BH + boff + (uint32_t)(16 * j) * 64); \
                bh[2 * j][0] = r0; bh[2 * j][1] = r1;                             \
                bh[2 * j + 1][0] = r2; bh[2 * j + 1][1] = r3;                     \
                ldsm_x4(r0, r1, r2, r3, sb + G_BL + boff + (uint32_t)(16 * j) * 64); \
                bl[2 * j][0] = r0; bl[2 * j][1] = r1;                             \
                bl[2 * j + 1][0] = r2; bl[2 * j + 1][1] = r3;                     \
            }                                                                     \
            _Pragma("unroll")                                                     \
            for (int i = 0; i < 4; i++)                                           \
                _Pragma("unroll")                                                 \
                for (int t = 0; t < 4; t++) {                                     \
                    mma_bf16(acc[i][t], ah[i], bh[t]);                            \
                    mma_bf16(acc[i][t], al[i], bh[t]);                            \
                    mma_bf16(acc[i][t], ah[i], bl[t]);                            \
                }                                                                 \
        }                                                                         \
        __syncthreads();                                                          \
        if (kc + 2 < KC) load_stage(kc & 1);                                      \
        CP_COMMIT();                                                              \
        if (kc + 1 < KC) { CP_WAIT1(); __syncthreads(); }                         \
    }                                                                             \
    const int gr = lane >> 2, gc = (lane & 3) * 2;

// ---------------------------------------------------------------------------
// GEMM (R12-identical): mode 0 fp32 C; mode 1 rope + hi/lo bf16
// ---------------------------------------------------------------------------
__global__ __launch_bounds__(128, 4)
void gemm_bf16_kernel(const __nv_bfloat16* __restrict__ Ah_g,
                      const __nv_bfloat16* __restrict__ Al_g,
                      const __nv_bfloat16* __restrict__ Bh_g,
                      const __nv_bfloat16* __restrict__ Bl_g,
                      float* __restrict__ C,
                      __nv_bfloat16* __restrict__ Chi, __nv_bfloat16* __restrict__ Clo,
                      int N, int K, int ldc, int mode)
{
    GEMM_MAINLOOP_BODY
    if (mode == 0) {
        #pragma unroll
        for (int i = 0; i < 4; i++) {
            const int row0 = m0 + wm + i * 16 + gr;
            #pragma unroll
            for (int t = 0; t < 4; t++) {
                const int col = n0 + wn + t * 8 + gc;
                if (col < N) {
                    *(float2*)(C + (size_t)row0 * ldc + col) =
                        make_float2(acc[i][t][0], acc[i][t][1]);
                    *(float2*)(C + (size_t)(row0 + 8) * ldc + col) =
                        make_float2(acc[i][t][2], acc[i][t][3]);
                }
            }
        }
    } else {
        #pragma unroll
        for (int i = 0; i < 4; i++) {
            const int row0 = m0 + wm + i * 16 + gr;
            #pragma unroll
            for (int t = 0; t < 4; t++) {
                const int col = n0 + wn + t * 8 + gc;
                const int d = col % DQK;
                #pragma unroll
                for (int rr = 0; rr < 2; rr++) {
                    const int row = row0 + rr * 8;
                    float v0 = acc[i][t][rr * 2 + 0];
                    float v1 = acc[i][t][rr * 2 + 1];
                    if (d >= DN) {
                        const int fi = (d - DN) >> 1;
                        const float f = (float)(row & (S_ - 1)) * g_freq[fi];
                        float sn, cs;
                        sincosf(f, &sn, &cs);
                        const float e = v0, o = v1;
                        v0 = e * cs - o * sn;
                        v1 = e * sn + o * cs;
                    }
                    __nv_bfloat162 hi, lo;
                    hl_split2(v0, v1, hi, lo);
                    *(__nv_bfloat162*)(Chi + (size_t)row * ldc + col) = hi;
                    *(__nv_bfloat162*)(Clo + (size_t)row * ldc + col) = lo;
                }
            }
        }
    }
}

// ---------------------------------------------------------------------------
// kv GEMM (separate function): fp32 kv_c + rope'd pe broadcast to kh/kl
// ---------------------------------------------------------------------------
__global__ __launch_bounds__(128, 4)
void gemm_kv_kernel(const __nv_bfloat16* __restrict__ Ah_g,
                    const __nv_bfloat16* __restrict__ Al_g,
                    const __nv_bfloat16* __restrict__ Bh_g,
                    const __nv_bfloat16* __restrict__ Bl_g,
                    float* __restrict__ C,
                    __nv_bfloat16* __restrict__ KhO, __nv_bfloat16* __restrict__ KlO,
                    int N, int K, int ldc)
{
    GEMM_MAINLOOP_BODY
    #pragma unroll
    for (int i = 0; i < 4; i++) {
        const int row0 = m0 + wm + i * 16 + gr;
        #pragma unroll
        for (int t = 0; t < 4; t++) {
            const int col = n0 + wn + t * 8 + gc;
            #pragma unroll
            for (int rr = 0; rr < 2; rr++) {
                const int row = row0 + rr * 8;
                float v0 = acc[i][t][rr * 2 + 0];
                float v1 = acc[i][t][rr * 2 + 1];
                if (col < KVL) {
                    *(float2*)(C + (size_t)row * ldc + col) = make_float2(v0, v1);
                } else if (col < KVL + DR) {
                    const int fi = (col - KVL) >> 1;
                    const float f = (float)(row & (S_ - 1)) * g_freq[fi];
                    float sn, cs;
                    sincosf(f, &sn, &cs);
                    const float e = v0, o = v1;
                    v0 = e * cs - o * sn;
                    v1 = e * sn + o * cs;
                    __nv_bfloat162 hi, lo;
                    hl_split2(v0, v1, hi, lo);
                    const size_t base = (size_t)row * NH_ * DQK + DN + (col - KVL);
                    #pragma unroll
                    for (int h16 = 0; h16 < NH_; h16++) {
                        *(__nv_bfloat162*)(KhO + base + (size_t)h16 * DQK) = hi;
                        *(__nv_bfloat162*)(KlO + base + (size_t)h16 * DQK) = lo;
                    }
                }
            }
        }
    }
}

// ---------------------------------------------------------------------------
// kvx GEMM (separate function): k-nope -> kh/kl [row][h][192], V -> vr hi/lo
// ---------------------------------------------------------------------------
__global__ __launch_bounds__(128, 4)
void gemm_kvx_kernel(const __nv_bfloat16* __restrict__ Ah_g,
                     const __nv_bfloat16* __restrict__ Al_g,
                     const __nv_bfloat16* __restrict__ Bh_g,
                     const __nv_bfloat16* __restrict__ Bl_g,
                     __nv_bfloat16* __restrict__ KhO, __nv_bfloat16* __restrict__ KlO,
                     __nv_bfloat16* __restrict__ Vh, __nv_bfloat16* __restrict__ Vl,
                     int K)
{
    GEMM_MAINLOOP_BODY
    #pragma unroll
    for (int i = 0; i < 4; i++) {
        const int row0 = m0 + wm + i * 16 + gr;
        #pragma unroll
        for (int t = 0; t < 4; t++) {
            const int col = n0 + wn + t * 8 + gc;
            const int hh = col >> 8, d = col & 255;
            #pragma unroll
            for (int rr = 0; rr < 2; rr++) {
                const int row = row0 + rr * 8;
                __nv_bfloat162 hi, lo;
                hl_split2(acc[i][t][rr * 2 + 0], acc[i][t][rr * 2 + 1], hi, lo);
                if (d < DN) {
                    const size_t o = ((size_t)row * NH_ + hh) * DQK + d;
                    *(__nv_bfloat162*)(KhO + o) = hi;
                    *(__nv_bfloat162*)(KlO + o) = lo;
                } else {
                    const size_t o = (size_t)row * (NH_ * DV) + hh * DV + (d - DN);
                    *(__nv_bfloat162*)(Vh + o) = hi;
                    *(__nv_bfloat162*)(Vl + o) = lo;
                }
            }
        }
    }
}

// ---------------------------------------------------------------------------
// freq init
// ---------------------------------------------------------------------------
__global__ void freq_init_kernel()
{
    if (threadIdx.x < 32)
        g_freq[threadIdx.x] = (float)pow(10000.0, -(double)threadIdx.x / 32.0);
}

// ---------------------------------------------------------------------------
// V transpose (bf16 hi/lo): vr [row][h][128] -> vt [b][h][dv][s]
// ---------------------------------------------------------------------------
__global__ void convvt2_kernel(const __nv_bfloat16* __restrict__ vrh,
                               const __nv_bfloat16* __restrict__ vrl,
                               __nv_bfloat16* __restrict__ vth,
                               __nv_bfloat16* __restrict__ vtl)
{
    __shared__ __nv_bfloat16 th[32][33], tl[32][33];
    const int bh = blockIdx.z;
    const int b = bh >> 4, h = bh & 15;
    const int s0 = blockIdx.x * 32, dv0 = blockIdx.y * 32;
    const int tx = threadIdx.x, ty = threadIdx.y;
    #pragma unroll
    for (int j = 0; j < 4; j++) {
        const int s = s0 + ty + 8 * j;
        const size_t o = (size_t)(b * S_ + s) * (NH_ * DV) + h * DV + dv0 + tx;
        th[ty + 8 * j][tx] = vrh[o];
        tl[ty + 8 * j][tx] = vrl[o];
    }
    __syncthreads();
    #pragma unroll
    for (int j = 0; j < 4; j++) {
        const int dv = dv0 + ty + 8 * j;
        const size_t o = ((size_t)bh * DV + dv) * S_ + s0 + tx;
        vth[o] = th[tx][ty + 8 * j];
        vtl[o] = tl[tx][ty + 8 * j];
    }
}

// ---------------------------------------------------------------------------
// Flash attention on HMMA (R11/R12 proven) — unchanged
// ---------------------------------------------------------------------------
__global__ __launch_bounds__(256, 1)
void flash_mma_kernel(const __nv_bfloat16* __restrict__ qh, const __nv_bfloat16* __restrict__ ql,
                      const __nv_bfloat16* __restrict__ kh, const __nv_bfloat16* __restrict__ kl,
                      const __nv_bfloat16* __restrict__ vth, const __nv_bfloat16* __restrict__ vtl,
                      __nv_bfloat16* __restrict__ ohi, __nv_bfloat16* __restrict__ olo)
{
    extern __shared__ __align__(128) char sm[];
    const uint32_t sb = smem_u32(sm);
    const int tid = threadIdx.x, warp = tid >> 5, lane = tid & 31;
    const int h = blockIdx.y, b = blockIdx.z;
    const int q0 = blockIdx.x * 128;
    const int wr = warp * 16;

    auto load_k = [&](int kt) {
        for (int u = tid; u < 64 * 24; u += 256) {
            const int r = u / 24, c = u % 24;
            const size_t off = ((size_t)(b * S_ + kt + r) * NH_ + h) * 192 + c * 8;
            cp_async16(sb + SM_KH + r * 400 + c * 16, kh + off);
            cp_async16(sb + SM_KL + r * 400 + c * 16, kl + off);
        }
    };
    auto load_v = [&](int kt) {
        for (int u = tid; u < 128 * 8; u += 256) {
            const int dv = u / 8, ck = u % 8;
            const size_t off = ((size_t)(b * NH_ + h) * DV + dv) * S_ + kt + ck * 8;
            cp_async16(sb + SM_VH + dv * 144 + ck * 16, vth + off);
            cp_async16(sb + SM_VL + dv * 144 + ck * 16, vtl + off);
        }
    };

    for (int u = tid; u < 128 * 24; u += 256) {
        const int r = u / 24, c = u % 24;
        const size_t off = ((size_t)(b * S_ + q0 + r) * NH_ + h) * 192 + c * 8;
        cp_async16(sb + SM_QH + r * 400 + c * 16, qh + off);
        cp_async16(sb + SM_QL + r * 400 + c * 16, ql + off);
    }
    load_k(0);
    CP_COMMIT();
    load_v(0);
    CP_COMMIT();

    float oacc[16][4];
    #pragma unroll
    for (int i = 0; i < 16; i++)
        #pragma unroll
        for (int j = 0; j < 4; j++) oacc[i][j] = 0.f;
    float m0 = -1e30f, m1 = -1e30f, l0 = 0.f, l1 = 0.f;

    const uint32_t aQoff = (uint32_t)(wr + (lane & 15)) * 400 + ((lane >> 4) << 4);
    const int rB8  = (lane & 7) + ((lane >> 4) << 3);
    const uint32_t bKoff = (uint32_t)rB8 * 400 + (((lane >> 3) & 1) << 4);
    const uint32_t bVoff = (uint32_t)rB8 * 144 + (((lane >> 3) & 1) << 4);

    for (int kt = 0; kt < S_; kt += 64) {
        const bool has_next = (kt + 64 < S_);
        CP_WAIT1();
        __syncthreads();

        float sacc[8][4];
        #pragma unroll
        for (int i = 0; i < 8; i++)
            #pragma unroll
            for (int j = 0; j < 4; j++) sacc[i][j] = 0.f;

        #pragma unroll
        for (int ks = 0; ks < 12; ks++) {
            uint32_t ah[4], al[4];
            ldsm_x4(ah[0], ah[1], ah[2], ah[3], sb + SM_QH + aQoff + ks * 32);
            ldsm_x4(al[0], al[1], al[2], al[3], sb + SM_QL + aQoff + ks * 32);
            #pragma unroll
            for (int g = 0; g < 4; g++) {
                uint32_t h0, h1, h2, h3, l0r, l1r, l2r, l3r;
                ldsm_x4(h0, h1, h2, h3,
                        sb + SM_KH + bKoff + (uint32_t)g * 16 * 400 + ks * 32);
                ldsm_x4(l0r, l1r, l2r, l3r,
                        sb + SM_KL + bKoff + (uint32_t)g * 16 * 400 + ks * 32);
                uint32_t bh0[2] = {h0, h1}, bh1[2] = {h2, h3};
                uint32_t bl0[2] = {l0r, l1r}, bl1[2] = {l2r, l3r};
                mma_bf16(sacc[2 * g],     ah, bh0);
                mma_bf16(sacc[2 * g + 1], ah, bh1);
                mma_bf16(sacc[2 * g],     al, bh0);
                mma_bf16(sacc[2 * g + 1], al, bh1);
                mma_bf16(sacc[2 * g],     ah, bl0);
                mma_bf16(sacc[2 * g + 1], ah, bl1);
            }
        }

        __syncthreads();
        if (has_next) load_k(kt + 64);
        CP_COMMIT();

        float mx0 = -1e30f, mx1 = -1e30f;
        #pragma unroll
        for (int nt = 0; nt < 8; nt++) {
            #pragma unroll
            for (int j = 0; j < 4; j++) sacc[nt][j] *= SCALE;
            mx0 = fmaxf(mx0, fmaxf(sacc[nt][0], sacc[nt][1]));
            mx1 = fmaxf(mx1, fmaxf(sacc[nt][2], sacc[nt][3]));
        }
        mx0 = fmaxf(mx0, __shfl_xor_sync(0xffffffffu, mx0, 1));
        mx0 = fmaxf(mx0, __shfl_xor_sync(0xffffffffu, mx0, 2));
        mx1 = fmaxf(mx1, __shfl_xor_sync(0xffffffffu, mx1, 1));
        mx1 = fmaxf(mx1, __shfl_xor_sync(0xffffffffu, mx1, 2));
        const float mn0 = fmaxf(m0, mx0), mn1 = fmaxf(m1, mx1);
        const float al0 = __expf(m0 - mn0), al1 = __expf(m1 - mn1);
        float rs0 = 0.f, rs1 = 0.f;
        #pragma unroll
        for (int nt = 0; nt < 8; nt++) {
            sacc[nt][0] = __expf(sacc[nt][0] - mn0);
            sacc[nt][1] = __expf(sacc[nt][1] - mn0);
            sacc[nt][2] = __expf(sacc[nt][2] - mn1);
            sacc[nt][3] = __expf(sacc[nt][3] - mn1);
            rs0 += sacc[nt][0] + sacc[nt][1];
            rs1 += sacc[nt][2] + sacc[nt][3];
        }
        rs0 += __shfl_xor_sync(0xffffffffu, rs0, 1);
        rs0 += __shfl_xor_sync(0xffffffffu, rs0, 2);
        rs1 += __shfl_xor_sync(0xffffffffu, rs1, 1);
        rs1 += __shfl_xor_sync(0xffffffffu, rs1, 2);
        l0 = l0 * al0 + rs0; m0 = mn0;
        l1 = l1 * al1 + rs1; m1 = mn1;
        #pragma unroll
        for (int nt = 0; nt < 16; nt++) {
            oacc[nt][0] *= al0; oacc[nt][1] *= al0;
            oacc[nt][2] *= al1; oacc[nt][3] *= al1;
        }

        if (has_next) { CP_WAIT1(); } else { CP_WAIT0(); }
        __syncthreads();

        #pragma unroll
        for (int kk = 0; kk < 4; kk++) {
            uint32_t ah[4], alr[4];
            {
                const float* p0 = sacc[2 * kk];
                const float* p1 = sacc[2 * kk + 1];
                float h00 = __bfloat162float(__float2bfloat16(p0[0]));
                float h01 = __bfloat162float(__float2bfloat16(p0[1]));
                float h02 = __bfloat162float(__float2bfloat16(p0[2]));
                float h03 = __bfloat162float(__float2bfloat16(p0[3]));
                float h10 = __bfloat162float(__float2bfloat16(p1[0]));
                float h11 = __bfloat162float(__float2bfloat16(p1[1]));
                float h12 = __bfloat162float(__float2bfloat16(p1[2]));
                float h13 = __bfloat162float(__float2bfloat16(p1[3]));
                ah[0] = pack_bf2(p0[0], p0[1]);
                ah[1] = pack_bf2(p0[2], p0[3]);
                ah[2] = pack_bf2(p1[0], p1[1]);
                ah[3] = pack_bf2(p1[2], p1[3]);
                alr[0] = pack_bf2(p0[0] - h00, p0[1] - h01);
                alr[1] = pack_bf2(p0[2] - h02, p0[3] - h03);
                alr[2] = pack_bf2(p1[0] - h10, p1[1] - h11);
                alr[3] = pack_bf2(p1[2] - h12, p1[3] - h13);
            }
            #pragma unroll
            for (int half = 0; half < 2; half++) {
                uint32_t bv[8][2];
                #pragma unroll
                for (int g = 0; g < 4; g++) {
                    uint32_t r0, r1, r2, r3;
                    ldsm_x4(r0, r1, r2, r3,
                            sb + SM_VH + bVoff + (uint32_t)(half * 64 + g * 16) * 144 + kk * 32);
                    bv[2 * g][0] = r0; bv[2 * g][1] = r1;
                    bv[2 * g + 1][0] = r2; bv[2 * g + 1][1] = r3;
                }
                #pragma unroll
                for (int t = 0; t < 8; t++) {
                    mma_bf16(oacc[half * 8 + t], ah, bv[t]);
                    mma_bf16(oacc[half * 8 + t], alr, bv[t]);
                }
                #pragma unroll
                for (int g = 0; g < 4; g++) {
                    uint32_t r0, r1, r2, r3;
                    ldsm_x4(r0, r1, r2, r3,
                            sb + SM_VL + bVoff + (uint32_t)(half * 64 + g * 16) * 144 + kk * 32);
                    bv[2 * g][0] = r0; bv[2 * g][1] = r1;
                    bv[2 * g + 1][0] = r2; bv[2 * g + 1][1] = r3;
                }
                #pragma unroll
                for (int t = 0; t < 8; t++)
                    mma_bf16(oacc[half * 8 + t], ah, bv[t]);
            }
        }

        __syncthreads();
        if (has_next) load_v(kt + 64);
        CP_COMMIT();
    }

    const float inv0 = 1.f / l0, inv1 = 1.f / l1;
    const int gr = lane >> 2, gc = (lane & 3) * 2;
    const int row0 = b * S_ + q0 + wr + gr;
    #pragma unroll
    for (int nt = 0; nt < 16; nt++) {
        const int col = h * DV + nt * 8 + gc;
        __nv_bfloat162 hi, lo;
        hl_split2(oacc[nt][0] * inv0, oacc[nt][1] * inv0, hi, lo);
        *(__nv_bfloat162*)(ohi + (size_t)row0 * (NH_ * DV) + col) = hi;
        *(__nv_bfloat162*)(olo + (size_t)row0 * (NH_ * DV) + col) = lo;
        hl_split2(oacc[nt][2] * inv1, oacc[nt][3] * inv1, hi, lo);
        *(__nv_bfloat162*)(ohi + (size_t)(row0 + 8) * (NH_ * DV) + col) = hi;
        *(__nv_bfloat162*)(olo + (size_t)(row0 + 8) * (NH_ * DV) + col) = lo;
    }
}

// ---------------------------------------------------------------------------
// Launcher
// ---------------------------------------------------------------------------
static inline void run_conv(const float* in, __nv_bfloat16* hi, __nv_bfloat16* lo,
                            int R, int Rpad, int Kin, int ldin)
{
    const int total = Rpad * (Kin / 4);
    conv_hl_kernel<<<(total + 255) / 256, 256>>>(in, hi, lo, R, Rpad, Kin, ldin);
}

extern "C" void kernel_launch(void* const* d_in, const int* in_sizes, int n_in,
                              void* d_out, int out_size)
{
    const float* hs    = (const float*)d_in[0];
    const float* wq_a  = (const float*)d_in[1];
    const float* qnw   = (const float*)d_in[2];
    const float* wq_b  = (const float*)d_in[3];
    const float* wkv_a = (const float*)d_in[4];
    const float* kvnw  = (const float*)d_in[5];
    const float* wkv_b = (const float*)d_in[6];
    const float* wo    = (const float*)d_in[7];
    float* out = (float*)d_out;

    void* p;
    cudaGetSymbolAddress(&p, g_qlora); float* qlora = (float*)p;
    cudaGetSymbolAddress(&p, g_kv);    float* kvbuf = (float*)p;
    cudaGetSymbolAddress(&p, g_a3);    __nv_bfloat16* a3 = (__nv_bfloat16*)p;
    cudaGetSymbolAddress(&p, g_b3);    __nv_bfloat16* b3 = (__nv_bfloat16*)p;
    cudaGetSymbolAddress(&p, g_qh);    __nv_bfloat16* qh = (__nv_bfloat16*)p;
    cudaGetSymbolAddress(&p, g_ql2);   __nv_bfloat16* ql = (__nv_bfloat16*)p;
    cudaGetSymbolAddress(&p, g_kh);    __nv_bfloat16* kh = (__nv_bfloat16*)p;
    cudaGetSymbolAddress(&p, g_kl);    __nv_bfloat16* kl = (__nv_bfloat16*)p;
    cudaGetSymbolAddress(&p, g_vrh);   __nv_bfloat16* vrh = (__nv_bfloat16*)p;
    cudaGetSymbolAddress(&p, g_vrl);   __nv_bfloat16* vrl = (__nv_bfloat16*)p;
    cudaGetSymbolAddress(&p, g_vth);   __nv_bfloat16* vth = (__nv_bfloat16*)p;
    cudaGetSymbolAddress(&p, g_vtl);   __nv_bfloat16* vtl = (__nv_bfloat16*)p;

    cudaFuncSetAttribute(flash_mma_kernel, cudaFuncAttributeMaxDynamicSharedMemorySize,
                         FLASH_SMEM);

    freq_init_kernel<<<1, 32>>>();

    // 1) q_lora = hs @ wq_a^T        [4096, 1536], K=2048
    run_conv(hs, a3, a3 + (size_t)BS * H_, BS, BS, H_, H_);
    run_conv(wq_a, b3, b3 + (size_t)QL * H_, QL, QL, H_, H_);
    gemm_bf16_kernel<<<dim3(QL / 64, BS / 128), 128>>>(
        a3, a3 + (size_t)BS * H_, b3, b3 + (size_t)QL * H_,
        qlora, nullptr, nullptr, QL, H_, QL, 0);

    // 2) kv = hs @ wkv_a^T  [4096, 576] (Npad 640): fp32 kv_c + rope'd pe -> kh/kl (bcast)
    run_conv(wkv_a, b3, b3 + (size_t)640 * H_, KVL + DR, 640, H_, H_);
    gemm_kv_kernel<<<dim3(640 / 64, BS / 128), 128>>>(
        a3, a3 + (size_t)BS * H_, b3, b3 + (size_t)640 * H_,
        kvbuf, kh, kl, KVL + DR, H_, KVL + DR);

    // 3) q = q_lora @ wq_b^T         [4096, 3072], K=1536; fused rope + hi/lo out
    rms_conv_hl_kernel<<<BS, 256>>>(qlora, qnw, a3, a3 + (size_t)BS * QL, QL, QL);
    run_conv(wq_b, b3, b3 + (size_t)3072 * QL, NH_ * DQK, NH_ * DQK, QL, QL);
    gemm_bf16_kernel<<<dim3((NH_ * DQK) / 64, BS / 128), 128>>>(
        a3, a3 + (size_t)BS * QL, b3, b3 + (size_t)3072 * QL,
        nullptr, qh, ql, NH_ * DQK, QL, NH_ * DQK, 1);

    // 4) kv_x = kv_c @ wkv_b^T       [4096, 4096], K=512: direct kh/kl + vrh/vrl out
    rms_conv_hl_kernel<<<BS, 256>>>(kvbuf, kvnw, a3, a3 + (size_t)BS * KVL, KVL, KVL + DR);
    run_conv(wkv_b, b3, b3 + (size_t)4096 * KVL, NH_ * (DN + DV), NH_ * (DN + DV), KVL, KVL);
    gemm_kvx_kernel<<<dim3((NH_ * (DN + DV)) / 64, BS / 128), 128>>>(
        a3, a3 + (size_t)BS * KVL, b3, b3 + (size_t)4096 * KVL,
        kh, kl, vrh, vrl, KVL);

    // 5) V transpose (bf16 hi/lo)
    convvt2_kernel<<<dim3(S_ / 32, DV / 32, B_ * NH_), dim3(32, 8)>>>(vrh, vrl, vth, vtl);

    // 6) flash attention -> a3 hi/lo directly (split-2 A for final GEMM)
    flash_mma_kernel<<<dim3(S_ / 128, NH_, B_), 256, FLASH_SMEM>>>(
        qh, ql, kh, kl, vth, vtl, a3, a3 + (size_t)BS * (NH_ * DV));

    // 7) out = attn @ wo^T           [4096, 2048], K=2048
    run_conv(wo, b3, b3 + (size_t)H_ * (NH_ * DV), H_, H_, NH_ * DV, NH_ * DV);
    gemm_bf16_kernel<<<dim3(H_ / 64, BS / 128), 128>>>(
        a3, a3 + (size_t)BS * (NH_ * DV), b3, b3 + (size_t)H_ * (NH_ * DV),
        out, nullptr, nullptr, H_, NH_ * DV, H_, 0);
}

// round 16
// speedup vs baseline: 1.0230x; 1.0110x over previous
#include <cuda_runtime.h>
#include <cuda_bf16.h>
#include <math.h>
#include <stdint.h>

// ---------------------------------------------------------------------------
// Problem constants (MLA prefill)
// ---------------------------------------------------------------------------
namespace {
constexpr int B_   = 2;
constexpr int S_   = 2048;
constexpr int H_   = 2048;
constexpr int NH_  = 16;
constexpr int QL   = 1536;
constexpr int KVL  = 512;
constexpr int DN   = 128;
constexpr int DR   = 64;
constexpr int DV   = 128;
constexpr int DQK  = 192;
constexpr int BS   = B_ * S_;
constexpr float SCALE = 0.07216878364870322f; // 1/sqrt(192)

constexpr int SM_QH  = 0;
constexpr int SM_QL  = SM_QH + 128 * 400;
constexpr int SM_KH  = SM_QL + 128 * 400;
constexpr int SM_KL  = SM_KH + 64 * 400;
constexpr int SM_VH  = SM_KL + 64 * 400;
constexpr int SM_VL  = SM_VH + 128 * 144;
constexpr int FLASH_SMEM = SM_VL + 128 * 144; // 190,464 B

// GEMM stage layout (bytes within one stage)
constexpr uint32_t G_AH = 0;       // 128 x 64B
constexpr uint32_t G_AL = 8192;    // 128 x 64B
constexpr uint32_t G_BH = 16384;   //  64 x 64B
constexpr uint32_t G_BL = 20480;   //  64 x 64B
constexpr uint32_t G_STG = 24576;  // 24 KB per stage, 2 stages = 48 KB
} // namespace

// ---------------------------------------------------------------------------
// Scratch (static device globals; no runtime allocation allowed)
// ---------------------------------------------------------------------------
__device__ float g_qlora[(size_t)BS * QL];
__device__ float g_kv[(size_t)BS * (KVL + DR)];   // only cols [0,512) valid
__device__ __nv_bfloat16 g_a3[(size_t)BS * 6144];    // activations [hi | lo]
__device__ __nv_bfloat16 g_b3[(size_t)3072 * 4608];  // weights     [hi | lo]
__device__ __nv_bfloat16 g_qh[(size_t)BS * NH_ * DQK];
__device__ __nv_bfloat16 g_ql2[(size_t)BS * NH_ * DQK];
__device__ __nv_bfloat16 g_kh[(size_t)BS * NH_ * DN];        // K nope hi [row][h][128]
__device__ __nv_bfloat16 g_kl[(size_t)BS * NH_ * DN];        // K nope lo
__device__ __nv_bfloat16 g_kpeh[(size_t)BS * DR];            // K pe hi (compact, shared)
__device__ __nv_bfloat16 g_kpel[(size_t)BS * DR];            // K pe lo
__device__ __nv_bfloat16 g_vrh[(size_t)BS * NH_ * DV];       // V row-major hi
__device__ __nv_bfloat16 g_vrl[(size_t)BS * NH_ * DV];       // V row-major lo
__device__ __nv_bfloat16 g_vth[(size_t)B_ * NH_ * DV * S_];  // [b][h][dv][s]
__device__ __nv_bfloat16 g_vtl[(size_t)B_ * NH_ * DV * S_];
__device__ float g_freq[32];

// ---------------------------------------------------------------------------
// Helpers
// ---------------------------------------------------------------------------
__device__ __forceinline__ uint32_t smem_u32(const void* p) {
    uint32_t a;
    asm("{ .reg .u64 t; cvta.to.shared.u64 t, %1; cvt.u32.u64 %0, t; }" : "=r"(a) : "l"(p));
    return a;
}
__device__ __forceinline__ void cp_async16(uint32_t dst, const void* src) {
    asm volatile("cp.async.cg.shared.global [%0], [%1], 16;" :: "r"(dst), "l"(src) : "memory");
}
#define CP_COMMIT() asm volatile("cp.async.commit_group;" ::: "memory")
#define CP_WAIT1()  asm volatile("cp.async.wait_group 1;" ::: "memory")
#define CP_WAIT0()  asm volatile("cp.async.wait_group 0;" ::: "memory")

__device__ __forceinline__ void ldsm_x4(uint32_t& r0, uint32_t& r1, uint32_t& r2, uint32_t& r3,
                                        uint32_t addr) {
    asm volatile("ldmatrix.sync.aligned.m8n8.x4.shared.b16 {%0,%1,%2,%3}, [%4];"
                 : "=r"(r0), "=r"(r1), "=r"(r2), "=r"(r3) : "r"(addr));
}
__device__ __forceinline__ void mma_bf16(float* c, const uint32_t* a, const uint32_t* b) {
    asm volatile("mma.sync.aligned.m16n8k16.row.col.f32.bf16.bf16.f32 "
                 "{%0,%1,%2,%3}, {%4,%5,%6,%7}, {%8,%9}, {%0,%1,%2,%3};"
                 : "+f"(c[0]), "+f"(c[1]), "+f"(c[2]), "+f"(c[3])
                 : "r"(a[0]), "r"(a[1]), "r"(a[2]), "r"(a[3]), "r"(b[0]), "r"(b[1]));
}
__device__ __forceinline__ uint32_t swoff(int r, int c) {
    return (uint32_t)(r * 64 + ((c ^ ((r >> 1) & 3)) << 4));
}
__device__ __forceinline__ uint32_t pack_bf2(float x, float y) {
    __nv_bfloat162 t(__float2bfloat16(x), __float2bfloat16(y));
    return *(uint32_t*)&t;
}
__device__ __forceinline__ void hl_split2(float v0, float v1,
                                          __nv_bfloat162& hi, __nv_bfloat162& lo) {
    __nv_bfloat16 h0 = __float2bfloat16(v0), h1 = __float2bfloat16(v1);
    hi = __nv_bfloat162(h0, h1);
    lo = __nv_bfloat162(__float2bfloat16(v0 - __bfloat162float(h0)),
                        __float2bfloat16(v1 - __bfloat162float(h1)));
}

// ---------------------------------------------------------------------------
// hi/lo split conversion (plain)
// ---------------------------------------------------------------------------
__global__ void conv_hl_kernel(const float* __restrict__ in,
                               __nv_bfloat16* __restrict__ hi_o,
                               __nv_bfloat16* __restrict__ lo_o,
                               int R, int Rpad, int Kin, int ldin)
{
    const int kq = Kin >> 2;
    const int idx = blockIdx.x * blockDim.x + threadIdx.x;
    if (idx >= Rpad * kq) return;
    const int row = idx / kq, cg = idx - row * kq;
    float4 v = make_float4(0.f, 0.f, 0.f, 0.f);
    if (row < R) v = *(const float4*)(in + (size_t)row * ldin + cg * 4);
    __nv_bfloat162 hiA, loA, hiB, loB;
    hl_split2(v.x, v.y, hiA, loA);
    hl_split2(v.z, v.w, hiB, loB);
    const size_t o = (size_t)row * Kin + cg * 4;
    *(__nv_bfloat162*)(hi_o + o + 0) = hiA;
    *(__nv_bfloat162*)(hi_o + o + 2) = hiB;
    *(__nv_bfloat162*)(lo_o + o + 0) = loA;
    *(__nv_bfloat162*)(lo_o + o + 2) = loB;
}

// ---------------------------------------------------------------------------
// Fused RMSNorm + hi/lo split
// ---------------------------------------------------------------------------
__global__ __launch_bounds__(256)
void rms_conv_hl_kernel(const float* __restrict__ x, const float* __restrict__ w,
                        __nv_bfloat16* __restrict__ hi_o, __nv_bfloat16* __restrict__ lo_o,
                        int n, int ld)
{
    const int row = blockIdx.x;
    const float* p = x + (size_t)row * ld;
    float ss = 0.f;
    for (int i = threadIdx.x; i < n; i += 256) { float v = p[i]; ss = fmaf(v, v, ss); }
    __shared__ float red[8];
    #pragma unroll
    for (int o = 16; o > 0; o >>= 1) ss += __shfl_xor_sync(0xffffffffu, ss, o);
    if ((threadIdx.x & 31) == 0) red[threadIdx.x >> 5] = ss;
    __syncthreads();
    __shared__ float s_inv;
    if (threadIdx.x == 0) {
        float t = 0.f;
        #pragma unroll
        for (int i = 0; i < 8; i++) t += red[i];
        s_inv = rsqrtf(t / (float)n + 1e-6f);
    }
    __syncthreads();
    const float inv = s_inv;
    for (int i = threadIdx.x * 2; i < n; i += 512) {
        const float v0 = w[i] * p[i] * inv;
        const float v1 = w[i + 1] * p[i + 1] * inv;
        __nv_bfloat162 hi, lo;
        hl_split2(v0, v1, hi, lo);
        *(__nv_bfloat162*)(hi_o + (size_t)row * n + i) = hi;
        *(__nv_bfloat162*)(lo_o + (size_t)row * n + i) = lo;
    }
}

// ===========================================================================
// GEMM mainloop body (shared text; each kernel below is a full copy so the
// mode-0/1 kernel keeps R12's exact codegen).
// ===========================================================================
#define GEMM_MAINLOOP_BODY                                                        \
    __shared__ __nv_bfloat16 smv[2][G_STG / 2];                                   \
    const int tid = threadIdx.x;                                                  \
    const int warp = tid >> 5, lane = tid & 31;                                   \
    const int m0 = blockIdx.y * 128, n0 = blockIdx.x * 64;                        \
    const int KC = K / 32;                                                        \
    const uint32_t sbase = smem_u32(&smv[0][0]);                                  \
    const int lr0 = tid >> 2, lc0 = tid & 3;                                      \
    const uint32_t so0 = swoff(lr0, lc0);                                         \
    const __nv_bfloat16* pAh = Ah_g + (size_t)(m0 + lr0) * K + lc0 * 8;           \
    const __nv_bfloat16* pAl = Al_g + (size_t)(m0 + lr0) * K + lc0 * 8;           \
    const __nv_bfloat16* pBh = Bh_g + (size_t)(n0 + lr0) * K + lc0 * 8;           \
    const __nv_bfloat16* pBl = Bl_g + (size_t)(n0 + lr0) * K + lc0 * 8;           \
    const size_t row32 = (size_t)32 * K;                                          \
    auto load_stage = [&](int s) {                                                \
        const uint32_t sb = sbase + s * G_STG;                                    \
        _Pragma("unroll")                                                         \
        for (int r = 0; r < 4; r++) {                                             \
            cp_async16(sb + G_AH + so0 + r * 2048, pAh + r * row32);              \
            cp_async16(sb + G_AL + so0 + r * 2048, pAl + r * row32);              \
        }                                                                         \
        _Pragma("unroll")                                                         \
        for (int r = 0; r < 2; r++) {                                             \
            cp_async16(sb + G_BH + so0 + r * 2048, pBh + r * row32);              \
            cp_async16(sb + G_BL + so0 + r * 2048, pBl + r * row32);              \
        }                                                                         \
        pAh += 32; pAl += 32; pBh += 32; pBl += 32;                               \
    };                                                                            \
    const int wm = (warp >> 1) * 64, wn = (warp & 1) * 32;                        \
    const int rA = wm + (lane & 15), cA = lane >> 4;                              \
    const int swzA = (rA >> 1) & 3;                                               \
    const int rB = wn + (lane & 7) + ((lane >> 4) << 3), cB = (lane >> 3) & 1;    \
    const int swzB = (rB >> 1) & 3;                                               \
    float acc[4][4][4];                                                           \
    _Pragma("unroll")                                                             \
    for (int i = 0; i < 4; i++)                                                   \
        _Pragma("unroll")                                                         \
        for (int j = 0; j < 4; j++)                                               \
            _Pragma("unroll")                                                     \
            for (int k = 0; k < 4; k++) acc[i][j][k] = 0.f;                       \
    load_stage(0); CP_COMMIT();                                                   \
    load_stage(1); CP_COMMIT();                                                   \
    CP_WAIT1();                                                                   \
    __syncthreads();                                                              \
    for (int kc = 0; kc < KC; kc++) {                                             \
        const uint32_t sb = sbase + (kc & 1) * G_STG;                             \
        _Pragma("unroll")                                                         \
        for (int h = 0; h < 2; h++) {                                             \
            const uint32_t aoff = (uint32_t)rA * 64 +                             \
                                  (uint32_t)(((h * 2 + cA) ^ swzA) << 4);         \
            const uint32_t boff = (uint32_t)rB * 64 +                             \
                                  (uint32_t)(((h * 2 + cB) ^ swzB) << 4);         \
            uint32_t ah[4][4], al[4][4], bh[4][2], bl[4][2];                      \
            _Pragma("unroll")                                                     \
            for (int i = 0; i < 4; i++) {                                         \
                ldsm_x4(ah[i][0], ah[i][1], ah[i][2], ah[i][3],                   \
                        sb + G_AH + aoff + (uint32_t)(16 * i) * 64);              \
                ldsm_x4(al[i][0], al[i][1], al[i][2], al[i][3],                   \
                        sb + G_AL + aoff + (uint32_t)(16 * i) * 64);              \
            }                                                                     \
            _Pragma("unroll")                                                     \
            for (int j = 0; j < 2; j++) {                                         \
                uint32_t r0, r1, r2, r3;                                          \
                ldsm_x4(r0, r1, r2, r3, sb + G_BH + boff + (uint32_t)(16 * j) * 64); \
                bh[2 * j][0] = r0; bh[2 * j][1] = r1;                             \
                bh[2 * j + 1][0] = r2; bh[2 * j + 1][1] = r3;                     \
                ldsm_x4(r0, r1, r2, r3, sb + G_BL + boff + (uint32_t)(16 * j) * 64); \
                bl[2 * j][0] = r0; bl[2 * j][1] = r1;                             \
                bl[2 * j + 1][0] = r2; bl[2 * j + 1][1] = r3;                     \
            }                                                                     \
            _Pragma("unroll")                                                     \
            for (int i = 0; i < 4; i++)                                           \
                _Pragma("unroll")                                                 \
                for (int t = 0; t < 4; t++) {                                     \
                    mma_bf16(acc[i][t], ah[i], bh[t]);                            \
                    mma_bf16(acc[i][t], al[i], bh[t]);                            \
                    mma_bf16(acc[i][t], ah[i], bl[t]);                            \
                }                                                                 \
        }                                                                         \
        __syncthreads();                                                          \
        if (kc + 2 < KC) load_stage(kc & 1);                                      \
        CP_COMMIT();                                                              \
        if (kc + 1 < KC) { CP_WAIT1(); __syncthreads(); }                         \
    }                                                                             \
    const int gr = lane >> 2, gc = (lane & 3) * 2;

// ---------------------------------------------------------------------------
// GEMM (R12-identical): mode 0 fp32 C; mode 1 rope + hi/lo bf16
// ---------------------------------------------------------------------------
__global__ __launch_bounds__(128, 4)
void gemm_bf16_kernel(const __nv_bfloat16* __restrict__ Ah_g,
                      const __nv_bfloat16* __restrict__ Al_g,
                      const __nv_bfloat16* __restrict__ Bh_g,
                      const __nv_bfloat16* __restrict__ Bl_g,
                      float* __restrict__ C,
                      __nv_bfloat16* __restrict__ Chi, __nv_bfloat16* __restrict__ Clo,
                      int N, int K, int ldc, int mode)
{
    GEMM_MAINLOOP_BODY
    if (mode == 0) {
        #pragma unroll
        for (int i = 0; i < 4; i++) {
            const int row0 = m0 + wm + i * 16 + gr;
            #pragma unroll
            for (int t = 0; t < 4; t++) {
                const int col = n0 + wn + t * 8 + gc;
                if (col < N) {
                    *(float2*)(C + (size_t)row0 * ldc + col) =
                        make_float2(acc[i][t][0], acc[i][t][1]);
                    *(float2*)(C + (size_t)(row0 + 8) * ldc + col) =
                        make_float2(acc[i][t][2], acc[i][t][3]);
                }
            }
        }
    } else {
        #pragma unroll
        for (int i = 0; i < 4; i++) {
            const int row0 = m0 + wm + i * 16 + gr;
            #pragma unroll
            for (int t = 0; t < 4; t++) {
                const int col = n0 + wn + t * 8 + gc;
                const int d = col % DQK;
                #pragma unroll
                for (int rr = 0; rr < 2; rr++) {
                    const int row = row0 + rr * 8;
                    float v0 = acc[i][t][rr * 2 + 0];
                    float v1 = acc[i][t][rr * 2 + 1];
                    if (d >= DN) {
                        const int fi = (d - DN) >> 1;
                        const float f = (float)(row & (S_ - 1)) * g_freq[fi];
                        float sn, cs;
                        sincosf(f, &sn, &cs);
                        const float e = v0, o = v1;
                        v0 = e * cs - o * sn;
                        v1 = e * sn + o * cs;
                    }
                    __nv_bfloat162 hi, lo;
                    hl_split2(v0, v1, hi, lo);
                    *(__nv_bfloat162*)(Chi + (size_t)row * ldc + col) = hi;
                    *(__nv_bfloat162*)(Clo + (size_t)row * ldc + col) = lo;
                }
            }
        }
    }
}

// ---------------------------------------------------------------------------
// kv GEMM: fp32 kv_c + rope'd pe -> COMPACT kpe hi/lo [row][64]
// ---------------------------------------------------------------------------
__global__ __launch_bounds__(128, 4)
void gemm_kv_kernel(const __nv_bfloat16* __restrict__ Ah_g,
                    const __nv_bfloat16* __restrict__ Al_g,
                    const __nv_bfloat16* __restrict__ Bh_g,
                    const __nv_bfloat16* __restrict__ Bl_g,
                    float* __restrict__ C,
                    __nv_bfloat16* __restrict__ KpeH, __nv_bfloat16* __restrict__ KpeL,
                    int N, int K, int ldc)
{
    GEMM_MAINLOOP_BODY
    #pragma unroll
    for (int i = 0; i < 4; i++) {
        const int row0 = m0 + wm + i * 16 + gr;
        #pragma unroll
        for (int t = 0; t < 4; t++) {
            const int col = n0 + wn + t * 8 + gc;
            #pragma unroll
            for (int rr = 0; rr < 2; rr++) {
                const int row = row0 + rr * 8;
                float v0 = acc[i][t][rr * 2 + 0];
                float v1 = acc[i][t][rr * 2 + 1];
                if (col < KVL) {
                    *(float2*)(C + (size_t)row * ldc + col) = make_float2(v0, v1);
                } else if (col < KVL + DR) {
                    const int fi = (col - KVL) >> 1;
                    const float f = (float)(row & (S_ - 1)) * g_freq[fi];
                    float sn, cs;
                    sincosf(f, &sn, &cs);
                    const float e = v0, o = v1;
                    v0 = e * cs - o * sn;
                    v1 = e * sn + o * cs;
                    __nv_bfloat162 hi, lo;
                    hl_split2(v0, v1, hi, lo);
                    const size_t o2 = (size_t)row * DR + (col - KVL);
                    *(__nv_bfloat162*)(KpeH + o2) = hi;
                    *(__nv_bfloat162*)(KpeL + o2) = lo;
                }
            }
        }
    }
}

// ---------------------------------------------------------------------------
// kvx GEMM: k-nope -> kh/kl [row][h][128], V -> vr hi/lo
// ---------------------------------------------------------------------------
__global__ __launch_bounds__(128, 4)
void gemm_kvx_kernel(const __nv_bfloat16* __restrict__ Ah_g,
                     const __nv_bfloat16* __restrict__ Al_g,
                     const __nv_bfloat16* __restrict__ Bh_g,
                     const __nv_bfloat16* __restrict__ Bl_g,
                     __nv_bfloat16* __restrict__ KhO, __nv_bfloat16* __restrict__ KlO,
                     __nv_bfloat16* __restrict__ Vh, __nv_bfloat16* __restrict__ Vl,
                     int K)
{
    GEMM_MAINLOOP_BODY
    #pragma unroll
    for (int i = 0; i < 4; i++) {
        const int row0 = m0 + wm + i * 16 + gr;
        #pragma unroll
        for (int t = 0; t < 4; t++) {
            const int col = n0 + wn + t * 8 + gc;
            const int hh = col >> 8, d = col & 255;
            #pragma unroll
            for (int rr = 0; rr < 2; rr++) {
                const int row = row0 + rr * 8;
                __nv_bfloat162 hi, lo;
                hl_split2(acc[i][t][rr * 2 + 0], acc[i][t][rr * 2 + 1], hi, lo);
                if (d < DN) {
                    const size_t o = ((size_t)row * NH_ + hh) * DN + d;
                    *(__nv_bfloat162*)(KhO + o) = hi;
                    *(__nv_bfloat162*)(KlO + o) = lo;
                } else {
                    const size_t o = (size_t)row * (NH_ * DV) + hh * DV + (d - DN);
                    *(__nv_bfloat162*)(Vh + o) = hi;
                    *(__nv_bfloat162*)(Vl + o) = lo;
                }
            }
        }
    }
}

// ---------------------------------------------------------------------------
// freq init
// ---------------------------------------------------------------------------
__global__ void freq_init_kernel()
{
    if (threadIdx.x < 32)
        g_freq[threadIdx.x] = (float)pow(10000.0, -(double)threadIdx.x / 32.0);
}

// ---------------------------------------------------------------------------
// V transpose (bf16 hi/lo): vr [row][h][128] -> vt [b][h][dv][s]
// ---------------------------------------------------------------------------
__global__ void convvt2_kernel(const __nv_bfloat16* __restrict__ vrh,
                               const __nv_bfloat16* __restrict__ vrl,
                               __nv_bfloat16* __restrict__ vth,
                               __nv_bfloat16* __restrict__ vtl)
{
    __shared__ __nv_bfloat16 th[32][33], tl[32][33];
    const int bh = blockIdx.z;
    const int b = bh >> 4, h = bh & 15;
    const int s0 = blockIdx.x * 32, dv0 = blockIdx.y * 32;
    const int tx = threadIdx.x, ty = threadIdx.y;
    #pragma unroll
    for (int j = 0; j < 4; j++) {
        const int s = s0 + ty + 8 * j;
        const size_t o = (size_t)(b * S_ + s) * (NH_ * DV) + h * DV + dv0 + tx;
        th[ty + 8 * j][tx] = vrh[o];
        tl[ty + 8 * j][tx] = vrl[o];
    }
    __syncthreads();
    #pragma unroll
    for (int j = 0; j < 4; j++) {
        const int dv = dv0 + ty + 8 * j;
        const size_t o = ((size_t)bh * DV + dv) * S_ + s0 + tx;
        vth[o] = th[tx][ty + 8 * j];
        vtl[o] = tl[tx][ty + 8 * j];
    }
}

// ---------------------------------------------------------------------------
// Flash attention on HMMA. K tile assembled from k-nope [row][h][128] +
// compact pe [row][64]; QK/PV MMA paths unchanged (R11/R12 proven).
// ---------------------------------------------------------------------------
__global__ __launch_bounds__(256, 1)
void flash_mma_kernel(const __nv_bfloat16* __restrict__ qh, const __nv_bfloat16* __restrict__ ql,
                      const __nv_bfloat16* __restrict__ khn, const __nv_bfloat16* __restrict__ kln,
                      const __nv_bfloat16* __restrict__ kpeh, const __nv_bfloat16* __restrict__ kpel,
                      const __nv_bfloat16* __restrict__ vth, const __nv_bfloat16* __restrict__ vtl,
                      __nv_bfloat16* __restrict__ ohi, __nv_bfloat16* __restrict__ olo)
{
    extern __shared__ __align__(128) char sm[];
    const uint32_t sb = smem_u32(sm);
    const int tid = threadIdx.x, warp = tid >> 5, lane = tid & 31;
    const int h = blockIdx.y, b = blockIdx.z;
    const int q0 = blockIdx.x * 128;
    const int wr = warp * 16;

    auto load_k = [&](int kt) {
        for (int u = tid; u < 64 * 24; u += 256) {
            const int r = u / 24, c = u % 24;
            if (c < 16) {
                const size_t off = ((size_t)(b * S_ + kt + r) * NH_ + h) * DN + c * 8;
                cp_async16(sb + SM_KH + r * 400 + c * 16, khn + off);
                cp_async16(sb + SM_KL + r * 400 + c * 16, kln + off);
            } else {
                const size_t off = (size_t)(b * S_ + kt + r) * DR + (c - 16) * 8;
                cp_async16(sb + SM_KH + r * 400 + c * 16, kpeh + off);
                cp_async16(sb + SM_KL + r * 400 + c * 16, kpel + off);
            }
        }
    };
    auto load_v = [&](int kt) {
        for (int u = tid; u < 128 * 8; u += 256) {
            const int dv = u / 8, ck = u % 8;
            const size_t off = ((size_t)(b * NH_ + h) * DV + dv) * S_ + kt + ck * 8;
            cp_async16(sb + SM_VH + dv * 144 + ck * 16, vth + off);
            cp_async16(sb + SM_VL + dv * 144 + ck * 16, vtl + off);
        }
    };

    for (int u = tid; u < 128 * 24; u += 256) {
        const int r = u / 24, c = u % 24;
        const size_t off = ((size_t)(b * S_ + q0 + r) * NH_ + h) * 192 + c * 8;
        cp_async16(sb + SM_QH + r * 400 + c * 16, qh + off);
        cp_async16(sb + SM_QL + r * 400 + c * 16, ql + off);
    }
    load_k(0);
    CP_COMMIT();
    load_v(0);
    CP_COMMIT();

    float oacc[16][4];
    #pragma unroll
    for (int i = 0; i < 16; i++)
        #pragma unroll
        for (int j = 0; j < 4; j++) oacc[i][j] = 0.f;
    float m0 = -1e30f, m1 = -1e30f, l0 = 0.f, l1 = 0.f;

    const uint32_t aQoff = (uint32_t)(wr + (lane & 15)) * 400 + ((lane >> 4) << 4);
    const int rB8  = (lane & 7) + ((lane >> 4) << 3);
    const uint32_t bKoff = (uint32_t)rB8 * 400 + (((lane >> 3) & 1) << 4);
    const uint32_t bVoff = (uint32_t)rB8 * 144 + (((lane >> 3) & 1) << 4);

    for (int kt = 0; kt < S_; kt += 64) {
        const bool has_next = (kt + 64 < S_);
        CP_WAIT1();
        __syncthreads();

        float sacc[8][4];
        #pragma unroll
        for (int i = 0; i < 8; i++)
            #pragma unroll
            for (int j = 0; j < 4; j++) sacc[i][j] = 0.f;

        #pragma unroll
        for (int ks = 0; ks < 12; ks++) {
            uint32_t ah[4], al[4];
            ldsm_x4(ah[0], ah[1], ah[2], ah[3], sb + SM_QH + aQoff + ks * 32);
            ldsm_x4(al[0], al[1], al[2], al[3], sb + SM_QL + aQoff + ks * 32);
            #pragma unroll
            for (int g = 0; g < 4; g++) {
                uint32_t h0, h1, h2, h3, l0r, l1r, l2r, l3r;
                ldsm_x4(h0, h1, h2, h3,
                        sb + SM_KH + bKoff + (uint32_t)g * 16 * 400 + ks * 32);
                ldsm_x4(l0r, l1r, l2r, l3r,
                        sb + SM_KL + bKoff + (uint32_t)g * 16 * 400 + ks * 32);
                uint32_t bh0[2] = {h0, h1}, bh1[2] = {h2, h3};
                uint32_t bl0[2] = {l0r, l1r}, bl1[2] = {l2r, l3r};
                mma_bf16(sacc[2 * g],     ah, bh0);
                mma_bf16(sacc[2 * g + 1], ah, bh1);
                mma_bf16(sacc[2 * g],     al, bh0);
                mma_bf16(sacc[2 * g + 1], al, bh1);
                mma_bf16(sacc[2 * g],     ah, bl0);
                mma_bf16(sacc[2 * g + 1], ah, bl1);
            }
        }

        __syncthreads();
        if (has_next) load_k(kt + 64);
        CP_COMMIT();

        float mx0 = -1e30f, mx1 = -1e30f;
        #pragma unroll
        for (int nt = 0; nt < 8; nt++) {
            #pragma unroll
            for (int j = 0; j < 4; j++) sacc[nt][j] *= SCALE;
            mx0 = fmaxf(mx0, fmaxf(sacc[nt][0], sacc[nt][1]));
            mx1 = fmaxf(mx1, fmaxf(sacc[nt][2], sacc[nt][3]));
        }
        mx0 = fmaxf(mx0, __shfl_xor_sync(0xffffffffu, mx0, 1));
        mx0 = fmaxf(mx0, __shfl_xor_sync(0xffffffffu, mx0, 2));
        mx1 = fmaxf(mx1, __shfl_xor_sync(0xffffffffu, mx1, 1));
        mx1 = fmaxf(mx1, __shfl_xor_sync(0xffffffffu, mx1, 2));
        const float mn0 = fmaxf(m0, mx0), mn1 = fmaxf(m1, mx1);
        const float al0 = __expf(m0 - mn0), al1 = __expf(m1 - mn1);
        float rs0 = 0.f, rs1 = 0.f;
        #pragma unroll
        for (int nt = 0; nt < 8; nt++) {
            sacc[nt][0] = __expf(sacc[nt][0] - mn0);
            sacc[nt][1] = __expf(sacc[nt][1] - mn0);
            sacc[nt][2] = __expf(sacc[nt][2] - mn1);
            sacc[nt][3] = __expf(sacc[nt][3] - mn1);
            rs0 += sacc[nt][0] + sacc[nt][1];
            rs1 += sacc[nt][2] + sacc[nt][3];
        }
        rs0 += __shfl_xor_sync(0xffffffffu, rs0, 1);
        rs0 += __shfl_xor_sync(0xffffffffu, rs0, 2);
        rs1 += __shfl_xor_sync(0xffffffffu, rs1, 1);
        rs1 += __shfl_xor_sync(0xffffffffu, rs1, 2);
        l0 = l0 * al0 + rs0; m0 = mn0;
        l1 = l1 * al1 + rs1; m1 = mn1;
        #pragma unroll
        for (int nt = 0; nt < 16; nt++) {
            oacc[nt][0] *= al0; oacc[nt][1] *= al0;
            oacc[nt][2] *= al1; oacc[nt][3] *= al1;
        }

        if (has_next) { CP_WAIT1(); } else { CP_WAIT0(); }
        __syncthreads();

        #pragma unroll
        for (int kk = 0; kk < 4; kk++) {
            uint32_t ah[4], alr[4];
            {
                const float* p0 = sacc[2 * kk];
                const float* p1 = sacc[2 * kk + 1];
                float h00 = __bfloat162float(__float2bfloat16(p0[0]));
                float h01 = __bfloat162float(__float2bfloat16(p0[1]));
                float h02 = __bfloat162float(__float2bfloat16(p0[2]));
                float h03 = __bfloat162float(__float2bfloat16(p0[3]));
                float h10 = __bfloat162float(__float2bfloat16(p1[0]));
                float h11 = __bfloat162float(__float2bfloat16(p1[1]));
                float h12 = __bfloat162float(__float2bfloat16(p1[2]));
                float h13 = __bfloat162float(__float2bfloat16(p1[3]));
                ah[0] = pack_bf2(p0[0], p0[1]);
                ah[1] = pack_bf2(p0[2], p0[3]);
                ah[2] = pack_bf2(p1[0], p1[1]);
                ah[3] = pack_bf2(p1[2], p1[3]);
                alr[0] = pack_bf2(p0[0] - h00, p0[1] - h01);
                alr[1] = pack_bf2(p0[2] - h02, p0[3] - h03);
                alr[2] = pack_bf2(p1[0] - h10, p1[1] - h11);
                alr[3] = pack_bf2(p1[2] - h12, p1[3] - h13);
            }
            #pragma unroll
            for (int half = 0; half < 2; half++) {
                uint32_t bv[8][2];
                #pragma unroll
                for (int g = 0; g < 4; g++) {
                    uint32_t r0, r1, r2, r3;
                    ldsm_x4(r0, r1, r2, r3,
                            sb + SM_VH + bVoff + (uint32_t)(half * 64 + g * 16) * 144 + kk * 32);
                    bv[2 * g][0] = r0; bv[2 * g][1] = r1;
                    bv[2 * g + 1][0] = r2; bv[2 * g + 1][1] = r3;
                }
                #pragma unroll
                for (int t = 0; t < 8; t++) {
                    mma_bf16(oacc[half * 8 + t], ah, bv[t]);
                    mma_bf16(oacc[half * 8 + t], alr, bv[t]);
                }
                #pragma unroll
                for (int g = 0; g < 4; g++) {
                    uint32_t r0, r1, r2, r3;
                    ldsm_x4(r0, r1, r2, r3,
                            sb + SM_VL + bVoff + (uint32_t)(half * 64 + g * 16) * 144 + kk * 32);
                    bv[2 * g][0] = r0; bv[2 * g][1] = r1;
                    bv[2 * g + 1][0] = r2; bv[2 * g + 1][1] = r3;
                }
                #pragma unroll
                for (int t = 0; t < 8; t++)
                    mma_bf16(oacc[half * 8 + t], ah, bv[t]);
            }
        }

        __syncthreads();
        if (has_next) load_v(kt + 64);
        CP_COMMIT();
    }

    const float inv0 = 1.f / l0, inv1 = 1.f / l1;
    const int gr = lane >> 2, gc = (lane & 3) * 2;
    const int row0 = b * S_ + q0 + wr + gr;
    #pragma unroll
    for (int nt = 0; nt < 16; nt++) {
        const int col = h * DV + nt * 8 + gc;
        __nv_bfloat162 hi, lo;
        hl_split2(oacc[nt][0] * inv0, oacc[nt][1] * inv0, hi, lo);
        *(__nv_bfloat162*)(ohi + (size_t)row0 * (NH_ * DV) + col) = hi;
        *(__nv_bfloat162*)(olo + (size_t)row0 * (NH_ * DV) + col) = lo;
        hl_split2(oacc[nt][2] * inv1, oacc[nt][3] * inv1, hi, lo);
        *(__nv_bfloat162*)(ohi + (size_t)(row0 + 8) * (NH_ * DV) + col) = hi;
        *(__nv_bfloat162*)(olo + (size_t)(row0 + 8) * (NH_ * DV) + col) = lo;
    }
}

// ---------------------------------------------------------------------------
// Launcher
// ---------------------------------------------------------------------------
static inline void run_conv(const float* in, __nv_bfloat16* hi, __nv_bfloat16* lo,
                            int R, int Rpad, int Kin, int ldin)
{
    const int total = Rpad * (Kin / 4);
    conv_hl_kernel<<<(total + 255) / 256, 256>>>(in, hi, lo, R, Rpad, Kin, ldin);
}

extern "C" void kernel_launch(void* const* d_in, const int* in_sizes, int n_in,
                              void* d_out, int out_size)
{
    const float* hs    = (const float*)d_in[0];
    const float* wq_a  = (const float*)d_in[1];
    const float* qnw   = (const float*)d_in[2];
    const float* wq_b  = (const float*)d_in[3];
    const float* wkv_a = (const float*)d_in[4];
    const float* kvnw  = (const float*)d_in[5];
    const float* wkv_b = (const float*)d_in[6];
    const float* wo    = (const float*)d_in[7];
    float* out = (float*)d_out;

    void* p;
    cudaGetSymbolAddress(&p, g_qlora); float* qlora = (float*)p;
    cudaGetSymbolAddress(&p, g_kv);    float* kvbuf = (float*)p;
    cudaGetSymbolAddress(&p, g_a3);    __nv_bfloat16* a3 = (__nv_bfloat16*)p;
    cudaGetSymbolAddress(&p, g_b3);    __nv_bfloat16* b3 = (__nv_bfloat16*)p;
    cudaGetSymbolAddress(&p, g_qh);    __nv_bfloat16* qh = (__nv_bfloat16*)p;
    cudaGetSymbolAddress(&p, g_ql2);   __nv_bfloat16* ql = (__nv_bfloat16*)p;
    cudaGetSymbolAddress(&p, g_kh);    __nv_bfloat16* kh = (__nv_bfloat16*)p;
    cudaGetSymbolAddress(&p, g_kl);    __nv_bfloat16* kl = (__nv_bfloat16*)p;
    cudaGetSymbolAddress(&p, g_kpeh);  __nv_bfloat16* kpeh = (__nv_bfloat16*)p;
    cudaGetSymbolAddress(&p, g_kpel);  __nv_bfloat16* kpel = (__nv_bfloat16*)p;
    cudaGetSymbolAddress(&p, g_vrh);   __nv_bfloat16* vrh = (__nv_bfloat16*)p;
    cudaGetSymbolAddress(&p, g_vrl);   __nv_bfloat16* vrl = (__nv_bfloat16*)p;
    cudaGetSymbolAddress(&p, g_vth);   __nv_bfloat16* vth = (__nv_bfloat16*)p;
    cudaGetSymbolAddress(&p, g_vtl);   __nv_bfloat16* vtl = (__nv_bfloat16*)p;

    cudaFuncSetAttribute(flash_mma_kernel, cudaFuncAttributeMaxDynamicSharedMemorySize,
                         FLASH_SMEM);

    freq_init_kernel<<<1, 32>>>();

    // 1) q_lora = hs @ wq_a^T        [4096, 1536], K=2048
    run_conv(hs, a3, a3 + (size_t)BS * H_, BS, BS, H_, H_);
    run_conv(wq_a, b3, b3 + (size_t)QL * H_, QL, QL, H_, H_);
    gemm_bf16_kernel<<<dim3(QL / 64, BS / 128), 128>>>(
        a3, a3 + (size_t)BS * H_, b3, b3 + (size_t)QL * H_,
        qlora, nullptr, nullptr, QL, H_, QL, 0);

    // 2) kv = hs @ wkv_a^T  [4096, 576] (Npad 640): fp32 kv_c + rope'd pe -> compact kpe
    run_conv(wkv_a, b3, b3 + (size_t)640 * H_, KVL + DR, 640, H_, H_);
    gemm_kv_kernel<<<dim3(640 / 64, BS / 128), 128>>>(
        a3, a3 + (size_t)BS * H_, b3, b3 + (size_t)640 * H_,
        kvbuf, kpeh, kpel, KVL + DR, H_, KVL + DR);

    // 3) q = q_lora @ wq_b^T         [4096, 3072], K=1536; fused rope + hi/lo out
    rms_conv_hl_kernel<<<BS, 256>>>(qlora, qnw, a3, a3 + (size_t)BS * QL, QL, QL);
    run_conv(wq_b, b3, b3 + (size_t)3072 * QL, NH_ * DQK, NH_ * DQK, QL, QL);
    gemm_bf16_kernel<<<dim3((NH_ * DQK) / 64, BS / 128), 128>>>(
        a3, a3 + (size_t)BS * QL, b3, b3 + (size_t)3072 * QL,
        nullptr, qh, ql, NH_ * DQK, QL, NH_ * DQK, 1);

    // 4) kv_x = kv_c @ wkv_b^T       [4096, 4096], K=512: k-nope + V hi/lo out
    rms_conv_hl_kernel<<<BS, 256>>>(kvbuf, kvnw, a3, a3 + (size_t)BS * KVL, KVL, KVL + DR);
    run_conv(wkv_b, b3, b3 + (size_t)4096 * KVL, NH_ * (DN + DV), NH_ * (DN + DV), KVL, KVL);
    gemm_kvx_kernel<<<dim3((NH_ * (DN + DV)) / 64, BS / 128), 128>>>(
        a3, a3 + (size_t)BS * KVL, b3, b3 + (size_t)4096 * KVL,
        kh, kl, vrh, vrl, KVL);

    // 5) V transpose (bf16 hi/lo)
    convvt2_kernel<<<dim3(S_ / 32, DV / 32, B_ * NH_), dim3(32, 8)>>>(vrh, vrl, vth, vtl);

    // 6) flash attention -> a3 hi/lo directly (split-2 A for final GEMM)
    flash_mma_kernel<<<dim3(S_ / 128, NH_, B_), 256, FLASH_SMEM>>>(
        qh, ql, kh, kl, kpeh, kpel, vth, vtl, a3, a3 + (size_t)BS * (NH_ * DV));

    // 7) out = attn @ wo^T           [4096, 2048], K=2048
    run_conv(wo, b3, b3 + (size_t)H_ * (NH_ * DV), H_, H_, NH_ * DV, NH_ * DV);
    gemm_bf16_kernel<<<dim3(H_ / 64, BS / 128), 128>>>(
        a3, a3 + (size_t)BS * (NH_ * DV), b3, b3 + (size_t)H_ * (NH_ * DV),
        out, nullptr, nullptr, H_, NH_ * DV, H_, 0);
}

// round 17
// speedup vs baseline: 1.0308x; 1.0075x over previous
#include <cuda_runtime.h>
#include <cuda_bf16.h>
#include <math.h>
#include <stdint.h>

// ---------------------------------------------------------------------------
// Problem constants (MLA prefill)
// ---------------------------------------------------------------------------
namespace {
constexpr int B_   = 2;
constexpr int S_   = 2048;
constexpr int H_   = 2048;
constexpr int NH_  = 16;
constexpr int QL   = 1536;
constexpr int KVL  = 512;
constexpr int DN   = 128;
constexpr int DR   = 64;
constexpr int DV   = 128;
constexpr int DQK  = 192;
constexpr int BS   = B_ * S_;
constexpr float SCALE = 0.07216878364870322f; // 1/sqrt(192)

// flash smem: Qh/Ql [128][400B], Kh/Kl [64][400B], Vh/Vl row-major [64 key][272B]
constexpr int SM_QH  = 0;
constexpr int SM_QL  = SM_QH + 128 * 400;
constexpr int SM_KH  = SM_QL + 128 * 400;
constexpr int SM_KL  = SM_KH + 64 * 400;
constexpr int SM_VH  = SM_KL + 64 * 400;
constexpr int SM_VL  = SM_VH + 64 * 272;
constexpr int FLASH_SMEM = SM_VL + 64 * 272; // 188,416 B

// GEMM stage layout (bytes within one stage)
constexpr uint32_t G_AH = 0;       // 128 x 64B
constexpr uint32_t G_AL = 8192;    // 128 x 64B
constexpr uint32_t G_BH = 16384;   //  64 x 64B
constexpr uint32_t G_BL = 20480;   //  64 x 64B
constexpr uint32_t G_STG = 24576;  // 24 KB per stage, 2 stages = 48 KB
} // namespace

// ---------------------------------------------------------------------------
// Scratch (static device globals; no runtime allocation allowed)
// ---------------------------------------------------------------------------
__device__ float g_qlora[(size_t)BS * QL];
__device__ float g_kv[(size_t)BS * (KVL + DR)];   // only cols [0,512) valid
__device__ __nv_bfloat16 g_a3[(size_t)BS * 6144];    // activations [hi | lo]
__device__ __nv_bfloat16 g_b3[(size_t)3072 * 4608];  // weights     [hi | lo]
__device__ __nv_bfloat16 g_qh[(size_t)BS * NH_ * DQK];
__device__ __nv_bfloat16 g_ql2[(size_t)BS * NH_ * DQK];
__device__ __nv_bfloat16 g_kh[(size_t)BS * NH_ * DN];        // K nope hi [row][h][128]
__device__ __nv_bfloat16 g_kl[(size_t)BS * NH_ * DN];        // K nope lo
__device__ __nv_bfloat16 g_kpeh[(size_t)BS * DR];            // K pe hi (compact, shared)
__device__ __nv_bfloat16 g_kpel[(size_t)BS * DR];            // K pe lo
__device__ __nv_bfloat16 g_vrh[(size_t)BS * NH_ * DV];       // V row-major hi
__device__ __nv_bfloat16 g_vrl[(size_t)BS * NH_ * DV];       // V row-major lo
__device__ float g_freq[32];

// ---------------------------------------------------------------------------
// Helpers
// ---------------------------------------------------------------------------
__device__ __forceinline__ uint32_t smem_u32(const void* p) {
    uint32_t a;
    asm("{ .reg .u64 t; cvta.to.shared.u64 t, %1; cvt.u32.u64 %0, t; }" : "=r"(a) : "l"(p));
    return a;
}
__device__ __forceinline__ void cp_async16(uint32_t dst, const void* src) {
    asm volatile("cp.async.cg.shared.global [%0], [%1], 16;" :: "r"(dst), "l"(src) : "memory");
}
#define CP_COMMIT() asm volatile("cp.async.commit_group;" ::: "memory")
#define CP_WAIT1()  asm volatile("cp.async.wait_group 1;" ::: "memory")
#define CP_WAIT0()  asm volatile("cp.async.wait_group 0;" ::: "memory")

__device__ __forceinline__ void ldsm_x4(uint32_t& r0, uint32_t& r1, uint32_t& r2, uint32_t& r3,
                                        uint32_t addr) {
    asm volatile("ldmatrix.sync.aligned.m8n8.x4.shared.b16 {%0,%1,%2,%3}, [%4];"
                 : "=r"(r0), "=r"(r1), "=r"(r2), "=r"(r3) : "r"(addr));
}
__device__ __forceinline__ void ldsm_x4_t(uint32_t& r0, uint32_t& r1, uint32_t& r2, uint32_t& r3,
                                          uint32_t addr) {
    asm volatile("ldmatrix.sync.aligned.m8n8.x4.trans.shared.b16 {%0,%1,%2,%3}, [%4];"
                 : "=r"(r0), "=r"(r1), "=r"(r2), "=r"(r3) : "r"(addr));
}
__device__ __forceinline__ void mma_bf16(float* c, const uint32_t* a, const uint32_t* b) {
    asm volatile("mma.sync.aligned.m16n8k16.row.col.f32.bf16.bf16.f32 "
                 "{%0,%1,%2,%3}, {%4,%5,%6,%7}, {%8,%9}, {%0,%1,%2,%3};"
                 : "+f"(c[0]), "+f"(c[1]), "+f"(c[2]), "+f"(c[3])
                 : "r"(a[0]), "r"(a[1]), "r"(a[2]), "r"(a[3]), "r"(b[0]), "r"(b[1]));
}
__device__ __forceinline__ uint32_t swoff(int r, int c) {
    return (uint32_t)(r * 64 + ((c ^ ((r >> 1) & 3)) << 4));
}
__device__ __forceinline__ uint32_t pack_bf2(float x, float y) {
    __nv_bfloat162 t(__float2bfloat16(x), __float2bfloat16(y));
    return *(uint32_t*)&t;
}
__device__ __forceinline__ void hl_split2(float v0, float v1,
                                          __nv_bfloat162& hi, __nv_bfloat162& lo) {
    __nv_bfloat16 h0 = __float2bfloat16(v0), h1 = __float2bfloat16(v1);
    hi = __nv_bfloat162(h0, h1);
    lo = __nv_bfloat162(__float2bfloat16(v0 - __bfloat162float(h0)),
                        __float2bfloat16(v1 - __bfloat162float(h1)));
}

// ---------------------------------------------------------------------------
// hi/lo split conversion (plain)
// ---------------------------------------------------------------------------
__global__ void conv_hl_kernel(const float* __restrict__ in,
                               __nv_bfloat16* __restrict__ hi_o,
                               __nv_bfloat16* __restrict__ lo_o,
                               int R, int Rpad, int Kin, int ldin)
{
    const int kq = Kin >> 2;
    const int idx = blockIdx.x * blockDim.x + threadIdx.x;
    if (idx >= Rpad * kq) return;
    const int row = idx / kq, cg = idx - row * kq;
    float4 v = make_float4(0.f, 0.f, 0.f, 0.f);
    if (row < R) v = *(const float4*)(in + (size_t)row * ldin + cg * 4);
    __nv_bfloat162 hiA, loA, hiB, loB;
    hl_split2(v.x, v.y, hiA, loA);
    hl_split2(v.z, v.w, hiB, loB);
    const size_t o = (size_t)row * Kin + cg * 4;
    *(__nv_bfloat162*)(hi_o + o + 0) = hiA;
    *(__nv_bfloat162*)(hi_o + o + 2) = hiB;
    *(__nv_bfloat162*)(lo_o + o + 0) = loA;
    *(__nv_bfloat162*)(lo_o + o + 2) = loB;
}

// ---------------------------------------------------------------------------
// Fused RMSNorm + hi/lo split
// ---------------------------------------------------------------------------
__global__ __launch_bounds__(256)
void rms_conv_hl_kernel(const float* __restrict__ x, const float* __restrict__ w,
                        __nv_bfloat16* __restrict__ hi_o, __nv_bfloat16* __restrict__ lo_o,
                        int n, int ld)
{
    const int row = blockIdx.x;
    const float* p = x + (size_t)row * ld;
    float ss = 0.f;
    for (int i = threadIdx.x; i < n; i += 256) { float v = p[i]; ss = fmaf(v, v, ss); }
    __shared__ float red[8];
    #pragma unroll
    for (int o = 16; o > 0; o >>= 1) ss += __shfl_xor_sync(0xffffffffu, ss, o);
    if ((threadIdx.x & 31) == 0) red[threadIdx.x >> 5] = ss;
    __syncthreads();
    __shared__ float s_inv;
    if (threadIdx.x == 0) {
        float t = 0.f;
        #pragma unroll
        for (int i = 0; i < 8; i++) t += red[i];
        s_inv = rsqrtf(t / (float)n + 1e-6f);
    }
    __syncthreads();
    const float inv = s_inv;
    for (int i = threadIdx.x * 2; i < n; i += 512) {
        const float v0 = w[i] * p[i] * inv;
        const float v1 = w[i + 1] * p[i + 1] * inv;
        __nv_bfloat162 hi, lo;
        hl_split2(v0, v1, hi, lo);
        *(__nv_bfloat162*)(hi_o + (size_t)row * n + i) = hi;
        *(__nv_bfloat162*)(lo_o + (size_t)row * n + i) = lo;
    }
}

// ===========================================================================
// GEMM mainloop body (shared text; each kernel below is a full copy so the
// mode-0/1 kernel keeps R12's exact codegen).
// ===========================================================================
#define GEMM_MAINLOOP_BODY                                                        \
    __shared__ __nv_bfloat16 smv[2][G_STG / 2];                                   \
    const int tid = threadIdx.x;                                                  \
    const int warp = tid >> 5, lane = tid & 31;                                   \
    const int m0 = blockIdx.y * 128, n0 = blockIdx.x * 64;                        \
    const int KC = K / 32;                                                        \
    const uint32_t sbase = smem_u32(&smv[0][0]);                                  \
    const int lr0 = tid >> 2, lc0 = tid & 3;                                      \
    const uint32_t so0 = swoff(lr0, lc0);                                         \
    const __nv_bfloat16* pAh = Ah_g + (size_t)(m0 + lr0) * K + lc0 * 8;           \
    const __nv_bfloat16* pAl = Al_g + (size_t)(m0 + lr0) * K + lc0 * 8;           \
    const __nv_bfloat16* pBh = Bh_g + (size_t)(n0 + lr0) * K + lc0 * 8;           \
    const __nv_bfloat16* pBl = Bl_g + (size_t)(n0 + lr0) * K + lc0 * 8;           \
    const size_t row32 = (size_t)32 * K;                                          \
    auto load_stage = [&](int s) {                                                \
        const uint32_t sb = sbase + s * G_STG;                                    \
        _Pragma("unroll")                                                         \
        for (int r = 0; r < 4; r++) {                                             \
            cp_async16(sb + G_AH + so0 + r * 2048, pAh + r * row32);              \
            cp_async16(sb + G_AL + so0 + r * 2048, pAl + r * row32);              \
        }                                                                         \
        _Pragma("unroll")                                                         \
        for (int r = 0; r < 2; r++) {                                             \
            cp_async16(sb + G_BH + so0 + r * 2048, pBh + r * row32);              \
            cp_async16(sb + G_BL + so0 + r * 2048, pBl + r * row32);              \
        }                                                                         \
        pAh += 32; pAl += 32; pBh += 32; pBl += 32;                               \
    };                                                                            \
    const int wm = (warp >> 1) * 64, wn = (warp & 1) * 32;                        \
    const int rA = wm + (lane & 15), cA = lane >> 4;                              \
    const int swzA = (rA >> 1) & 3;                                               \
    const int rB = wn + (lane & 7) + ((lane >> 4) << 3), cB = (lane >> 3) & 1;    \
    const int swzB = (rB >> 1) & 3;                                               \
    float acc[4][4][4];                                                           \
    _Pragma("unroll")                                                             \
    for (int i = 0; i < 4; i++)                                                   \
        _Pragma("unroll")                                                         \
        for (int j = 0; j < 4; j++)                                               \
            _Pragma("unroll")                                                     \
            for (int k = 0; k < 4; k++) acc[i][j][k] = 0.f;                       \
    load_stage(0); CP_COMMIT();                                                   \
    load_stage(1); CP_COMMIT();                                                   \
    CP_WAIT1();                                                                   \
    __syncthreads();                                                              \
    for (int kc = 0; kc < KC; kc++) {                                             \
        const uint32_t sb = sbase + (kc & 1) * G_STG;                             \
        _Pragma("unroll")                                                         \
        for (int h = 0; h < 2; h++) {                                             \
            const uint32_t aoff = (uint32_t)rA * 64 +                             \
                                  (uint32_t)(((h * 2 + cA) ^ swzA) << 4);         \
            const uint32_t boff = (uint32_t)rB * 64 +                             \
                                  (uint32_t)(((h * 2 + cB) ^ swzB) << 4);         \
            uint32_t ah[4][4], al[4][4], bh[4][2], bl[4][2];                      \
            _Pragma("unroll")                                                     \
            for (int i = 0; i < 4; i++) {                                         \
                ldsm_x4(ah[i][0], ah[i][1], ah[i][2], ah[i][3],                   \
                        sb + G_AH + aoff + (uint32_t)(16 * i) * 64);              \
                ldsm_x4(al[i][0], al[i][1], al[i][2], al[i][3],                   \
                        sb + G_AL + aoff + (uint32_t)(16 * i) * 64);              \
            }                                                                     \
            _Pragma("unroll")                                                     \
            for (int j = 0; j < 2; j++) {                                         \
                uint32_t r0, r1, r2, r3;                                          \
                ldsm_x4(r0, r1, r2, r3, sb + G_BH + boff + (uint32_t)(16 * j) * 64); \
                bh[2 * j][0] = r0; bh[2 * j][1] = r1;                             \
                bh[2 * j + 1][0] = r2; bh[2 * j + 1][1] = r3;                     \
                ldsm_x4(r0, r1, r2, r3, sb + G_BL + boff + (uint32_t)(16 * j) * 64); \
                bl[2 * j][0] = r0; bl[2 * j][1] = r1;                             \
                bl[2 * j + 1][0] = r2; bl[2 * j + 1][1] = r3;                     \
            }                                                                     \
            _Pragma("unroll")                                                     \
            for (int i = 0; i < 4; i++)                                           \
                _Pragma("unroll")                                                 \
                for (int t = 0; t < 4; t++) {                                     \
                    mma_bf16(acc[i][t], ah[i], bh[t]);                            \
                    mma_bf16(acc[i][t], al[i], bh[t]);                            \
                    mma_bf16(acc[i][t], ah[i], bl[t]);                            \
                }                                                                 \
        }                                                                         \
        __syncthreads();                                                          \
        if (kc + 2 < KC) load_stage(kc & 1);                                      \
        CP_COMMIT();                                                              \
        if (kc + 1 < KC) { CP_WAIT1(); __syncthreads(); }                         \
    }                                                                             \
    const int gr = lane >> 2, gc = (lane & 3) * 2;

// ---------------------------------------------------------------------------
// GEMM (R12-identical): mode 0 fp32 C; mode 1 rope + hi/lo bf16
// ---------------------------------------------------------------------------
__global__ __launch_bounds__(128, 4)
void gemm_bf16_kernel(const __nv_bfloat16* __restrict__ Ah_g,
                      const __nv_bfloat16* __restrict__ Al_g,
                      const __nv_bfloat16* __restrict__ Bh_g,
                      const __nv_bfloat16* __restrict__ Bl_g,
                      float* __restrict__ C,
                      __nv_bfloat16* __restrict__ Chi, __nv_bfloat16* __restrict__ Clo,
                      int N, int K, int ldc, int mode)
{
    GEMM_MAINLOOP_BODY
    if (mode == 0) {
        #pragma unroll
        for (int i = 0; i < 4; i++) {
            const int row0 = m0 + wm + i * 16 + gr;
            #pragma unroll
            for (int t = 0; t < 4; t++) {
                const int col = n0 + wn + t * 8 + gc;
                if (col < N) {
                    *(float2*)(C + (size_t)row0 * ldc + col) =
                        make_float2(acc[i][t][0], acc[i][t][1]);
                    *(float2*)(C + (size_t)(row0 + 8) * ldc + col) =
                        make_float2(acc[i][t][2], acc[i][t][3]);
                }
            }
        }
    } else {
        #pragma unroll
        for (int i = 0; i < 4; i++) {
            const int row0 = m0 + wm + i * 16 + gr;
            #pragma unroll
            for (int t = 0; t < 4; t++) {
                const int col = n0 + wn + t * 8 + gc;
                const int d = col % DQK;
                #pragma unroll
                for (int rr = 0; rr < 2; rr++) {
                    const int row = row0 + rr * 8;
                    float v0 = acc[i][t][rr * 2 + 0];
                    float v1 = acc[i][t][rr * 2 + 1];
                    if (d >= DN) {
                        const int fi = (d - DN) >> 1;
                        const float f = (float)(row & (S_ - 1)) * g_freq[fi];
                        float sn, cs;
                        sincosf(f, &sn, &cs);
                        const float e = v0, o = v1;
                        v0 = e * cs - o * sn;
                        v1 = e * sn + o * cs;
                    }
                    __nv_bfloat162 hi, lo;
                    hl_split2(v0, v1, hi, lo);
                    *(__nv_bfloat162*)(Chi + (size_t)row * ldc + col) = hi;
                    *(__nv_bfloat162*)(Clo + (size_t)row * ldc + col) = lo;
                }
            }
        }
    }
}

// ---------------------------------------------------------------------------
// kv GEMM: fp32 kv_c + rope'd pe -> COMPACT kpe hi/lo [row][64]
// ---------------------------------------------------------------------------
__global__ __launch_bounds__(128, 4)
void gemm_kv_kernel(const __nv_bfloat16* __restrict__ Ah_g,
                    const __nv_bfloat16* __restrict__ Al_g,
                    const __nv_bfloat16* __restrict__ Bh_g,
                    const __nv_bfloat16* __restrict__ Bl_g,
                    float* __restrict__ C,
                    __nv_bfloat16* __restrict__ KpeH, __nv_bfloat16* __restrict__ KpeL,
                    int N, int K, int ldc)
{
    GEMM_MAINLOOP_BODY
    #pragma unroll
    for (int i = 0; i < 4; i++) {
        const int row0 = m0 + wm + i * 16 + gr;
        #pragma unroll
        for (int t = 0; t < 4; t++) {
            const int col = n0 + wn + t * 8 + gc;
            #pragma unroll
            for (int rr = 0; rr < 2; rr++) {
                const int row = row0 + rr * 8;
                float v0 = acc[i][t][rr * 2 + 0];
                float v1 = acc[i][t][rr * 2 + 1];
                if (col < KVL) {
                    *(float2*)(C + (size_t)row * ldc + col) = make_float2(v0, v1);
                } else if (col < KVL + DR) {
                    const int fi = (col - KVL) >> 1;
                    const float f = (float)(row & (S_ - 1)) * g_freq[fi];
                    float sn, cs;
                    sincosf(f, &sn, &cs);
                    const float e = v0, o = v1;
                    v0 = e * cs - o * sn;
                    v1 = e * sn + o * cs;
                    __nv_bfloat162 hi, lo;
                    hl_split2(v0, v1, hi, lo);
                    const size_t o2 = (size_t)row * DR + (col - KVL);
                    *(__nv_bfloat162*)(KpeH + o2) = hi;
                    *(__nv_bfloat162*)(KpeL + o2) = lo;
                }
            }
        }
    }
}

// ---------------------------------------------------------------------------
// kvx GEMM: k-nope -> kh/kl [row][h][128], V -> vr hi/lo (row-major)
// ---------------------------------------------------------------------------
__global__ __launch_bounds__(128, 4)
void gemm_kvx_kernel(const __nv_bfloat16* __restrict__ Ah_g,
                     const __nv_bfloat16* __restrict__ Al_g,
                     const __nv_bfloat16* __restrict__ Bh_g,
                     const __nv_bfloat16* __restrict__ Bl_g,
                     __nv_bfloat16* __restrict__ KhO, __nv_bfloat16* __restrict__ KlO,
                     __nv_bfloat16* __restrict__ Vh, __nv_bfloat16* __restrict__ Vl,
                     int K)
{
    GEMM_MAINLOOP_BODY
    #pragma unroll
    for (int i = 0; i < 4; i++) {
        const int row0 = m0 + wm + i * 16 + gr;
        #pragma unroll
        for (int t = 0; t < 4; t++) {
            const int col = n0 + wn + t * 8 + gc;
            const int hh = col >> 8, d = col & 255;
            #pragma unroll
            for (int rr = 0; rr < 2; rr++) {
                const int row = row0 + rr * 8;
                __nv_bfloat162 hi, lo;
                hl_split2(acc[i][t][rr * 2 + 0], acc[i][t][rr * 2 + 1], hi, lo);
                if (d < DN) {
                    const size_t o = ((size_t)row * NH_ + hh) * DN + d;
                    *(__nv_bfloat162*)(KhO + o) = hi;
                    *(__nv_bfloat162*)(KlO + o) = lo;
                } else {
                    const size_t o = (size_t)row * (NH_ * DV) + hh * DV + (d - DN);
                    *(__nv_bfloat162*)(Vh + o) = hi;
                    *(__nv_bfloat162*)(Vl + o) = lo;
                }
            }
        }
    }
}

// ---------------------------------------------------------------------------
// freq init
// ---------------------------------------------------------------------------
__global__ void freq_init_kernel()
{
    if (threadIdx.x < 32)
        g_freq[threadIdx.x] = (float)pow(10000.0, -(double)threadIdx.x / 32.0);
}

// ---------------------------------------------------------------------------
// Flash attention on HMMA. K from k-nope + compact pe; V consumed ROW-MAJOR
// via ldmatrix.trans (convvt eliminated). QK/PV MMA sets unchanged.
// ---------------------------------------------------------------------------
__global__ __launch_bounds__(256, 1)
void flash_mma_kernel(const __nv_bfloat16* __restrict__ qh, const __nv_bfloat16* __restrict__ ql,
                      const __nv_bfloat16* __restrict__ khn, const __nv_bfloat16* __restrict__ kln,
                      const __nv_bfloat16* __restrict__ kpeh, const __nv_bfloat16* __restrict__ kpel,
                      const __nv_bfloat16* __restrict__ vrh, const __nv_bfloat16* __restrict__ vrl,
                      __nv_bfloat16* __restrict__ ohi, __nv_bfloat16* __restrict__ olo)
{
    extern __shared__ __align__(128) char sm[];
    const uint32_t sb = smem_u32(sm);
    const int tid = threadIdx.x, warp = tid >> 5, lane = tid & 31;
    const int h = blockIdx.y, b = blockIdx.z;
    const int q0 = blockIdx.x * 128;
    const int wr = warp * 16;

    auto load_k = [&](int kt) {
        for (int u = tid; u < 64 * 24; u += 256) {
            const int r = u / 24, c = u % 24;
            if (c < 16) {
                const size_t off = ((size_t)(b * S_ + kt + r) * NH_ + h) * DN + c * 8;
                cp_async16(sb + SM_KH + r * 400 + c * 16, khn + off);
                cp_async16(sb + SM_KL + r * 400 + c * 16, kln + off);
            } else {
                const size_t off = (size_t)(b * S_ + kt + r) * DR + (c - 16) * 8;
                cp_async16(sb + SM_KH + r * 400 + c * 16, kpeh + off);
                cp_async16(sb + SM_KL + r * 400 + c * 16, kpel + off);
            }
        }
    };
    // V tile row-major [64 key][128 dv], pitch 272 B
    auto load_v = [&](int kt) {
        for (int u = tid; u < 64 * 16; u += 256) {
            const int r = u >> 4, ck = u & 15;
            const size_t off = (size_t)(b * S_ + kt + r) * (NH_ * DV) + h * DV + ck * 8;
            cp_async16(sb + SM_VH + r * 272 + ck * 16, vrh + off);
            cp_async16(sb + SM_VL + r * 272 + ck * 16, vrl + off);
        }
    };

    for (int u = tid; u < 128 * 24; u += 256) {
        const int r = u / 24, c = u % 24;
        const size_t off = ((size_t)(b * S_ + q0 + r) * NH_ + h) * 192 + c * 8;
        cp_async16(sb + SM_QH + r * 400 + c * 16, qh + off);
        cp_async16(sb + SM_QL + r * 400 + c * 16, ql + off);
    }
    load_k(0);
    CP_COMMIT();
    load_v(0);
    CP_COMMIT();

    float oacc[16][4];
    #pragma unroll
    for (int i = 0; i < 16; i++)
        #pragma unroll
        for (int j = 0; j < 4; j++) oacc[i][j] = 0.f;
    float m0 = -1e30f, m1 = -1e30f, l0 = 0.f, l1 = 0.f;

    const uint32_t aQoff = (uint32_t)(wr + (lane & 15)) * 400 + ((lane >> 4) << 4);
    const int rB8  = (lane & 7) + ((lane >> 4) << 3);
    const uint32_t bKoff = (uint32_t)rB8 * 400 + (((lane >> 3) & 1) << 4);
    // trans b-load: key row = lane&15, +16B dv offset for lanes >= 16
    const uint32_t bVoff = (uint32_t)(lane & 15) * 272 + ((lane >> 4) << 4);

    for (int kt = 0; kt < S_; kt += 64) {
        const bool has_next = (kt + 64 < S_);
        CP_WAIT1();
        __syncthreads();

        float sacc[8][4];
        #pragma unroll
        for (int i = 0; i < 8; i++)
            #pragma unroll
            for (int j = 0; j < 4; j++) sacc[i][j] = 0.f;

        #pragma unroll
        for (int ks = 0; ks < 12; ks++) {
            uint32_t ah[4], al[4];
            ldsm_x4(ah[0], ah[1], ah[2], ah[3], sb + SM_QH + aQoff + ks * 32);
            ldsm_x4(al[0], al[1], al[2], al[3], sb + SM_QL + aQoff + ks * 32);
            #pragma unroll
            for (int g = 0; g < 4; g++) {
                uint32_t h0, h1, h2, h3, l0r, l1r, l2r, l3r;
                ldsm_x4(h0, h1, h2, h3,
                        sb + SM_KH + bKoff + (uint32_t)g * 16 * 400 + ks * 32);
                ldsm_x4(l0r, l1r, l2r, l3r,
                        sb + SM_KL + bKoff + (uint32_t)g * 16 * 400 + ks * 32);
                uint32_t bh0[2] = {h0, h1}, bh1[2] = {h2, h3};
                uint32_t bl0[2] = {l0r, l1r}, bl1[2] = {l2r, l3r};
                mma_bf16(sacc[2 * g],     ah, bh0);
                mma_bf16(sacc[2 * g + 1], ah, bh1);
                mma_bf16(sacc[2 * g],     al, bh0);
                mma_bf16(sacc[2 * g + 1], al, bh1);
                mma_bf16(sacc[2 * g],     ah, bl0);
                mma_bf16(sacc[2 * g + 1], ah, bl1);
            }
        }

        __syncthreads();
        if (has_next) load_k(kt + 64);
        CP_COMMIT();

        float mx0 = -1e30f, mx1 = -1e30f;
        #pragma unroll
        for (int nt = 0; nt < 8; nt++) {
            #pragma unroll
            for (int j = 0; j < 4; j++) sacc[nt][j] *= SCALE;
            mx0 = fmaxf(mx0, fmaxf(sacc[nt][0], sacc[nt][1]));
            mx1 = fmaxf(mx1, fmaxf(sacc[nt][2], sacc[nt][3]));
        }
        mx0 = fmaxf(mx0, __shfl_xor_sync(0xffffffffu, mx0, 1));
        mx0 = fmaxf(mx0, __shfl_xor_sync(0xffffffffu, mx0, 2));
        mx1 = fmaxf(mx1, __shfl_xor_sync(0xffffffffu, mx1, 1));
        mx1 = fmaxf(mx1, __shfl_xor_sync(0xffffffffu, mx1, 2));
        const float mn0 = fmaxf(m0, mx0), mn1 = fmaxf(m1, mx1);
        const float al0 = __expf(m0 - mn0), al1 = __expf(m1 - mn1);
        float rs0 = 0.f, rs1 = 0.f;
        #pragma unroll
        for (int nt = 0; nt < 8; nt++) {
            sacc[nt][0] = __expf(sacc[nt][0] - mn0);
            sacc[nt][1] = __expf(sacc[nt][1] - mn0);
            sacc[nt][2] = __expf(sacc[nt][2] - mn1);
            sacc[nt][3] = __expf(sacc[nt][3] - mn1);
            rs0 += sacc[nt][0] + sacc[nt][1];
            rs1 += sacc[nt][2] + sacc[nt][3];
        }
        rs0 += __shfl_xor_sync(0xffffffffu, rs0, 1);
        rs0 += __shfl_xor_sync(0xffffffffu, rs0, 2);
        rs1 += __shfl_xor_sync(0xffffffffu, rs1, 1);
        rs1 += __shfl_xor_sync(0xffffffffu, rs1, 2);
        l0 = l0 * al0 + rs0; m0 = mn0;
        l1 = l1 * al1 + rs1; m1 = mn1;
        #pragma unroll
        for (int nt = 0; nt < 16; nt++) {
            oacc[nt][0] *= al0; oacc[nt][1] *= al0;
            oacc[nt][2] *= al1; oacc[nt][3] *= al1;
        }

        if (has_next) { CP_WAIT1(); } else { CP_WAIT0(); }
        __syncthreads();

        #pragma unroll
        for (int kk = 0; kk < 4; kk++) {
            uint32_t ah[4], alr[4];
            {
                const float* p0 = sacc[2 * kk];
                const float* p1 = sacc[2 * kk + 1];
                float h00 = __bfloat162float(__float2bfloat16(p0[0]));
                float h01 = __bfloat162float(__float2bfloat16(p0[1]));
                float h02 = __bfloat162float(__float2bfloat16(p0[2]));
                float h03 = __bfloat162float(__float2bfloat16(p0[3]));
                float h10 = __bfloat162float(__float2bfloat16(p1[0]));
                float h11 = __bfloat162float(__float2bfloat16(p1[1]));
                float h12 = __bfloat162float(__float2bfloat16(p1[2]));
                float h13 = __bfloat162float(__float2bfloat16(p1[3]));
                ah[0] = pack_bf2(p0[0], p0[1]);
                ah[1] = pack_bf2(p0[2], p0[3]);
                ah[2] = pack_bf2(p1[0], p1[1]);
                ah[3] = pack_bf2(p1[2], p1[3]);
                alr[0] = pack_bf2(p0[0] - h00, p0[1] - h01);
                alr[1] = pack_bf2(p0[2] - h02, p0[3] - h03);
                alr[2] = pack_bf2(p1[0] - h10, p1[1] - h11);
                alr[3] = pack_bf2(p1[2] - h12, p1[3] - h13);
            }
            const uint32_t vrow = bVoff + (uint32_t)kk * 16 * 272;
            #pragma unroll
            for (int half = 0; half < 2; half++) {
                uint32_t bv[8][2];
                #pragma unroll
                for (int g = 0; g < 4; g++) {
                    uint32_t r0, r1, r2, r3;
                    ldsm_x4_t(r0, r1, r2, r3,
                              sb + SM_VH + vrow + (uint32_t)(half * 128 + g * 32));
                    bv[2 * g][0] = r0; bv[2 * g][1] = r1;
                    bv[2 * g + 1][0] = r2; bv[2 * g + 1][1] = r3;
                }
                #pragma unroll
                for (int t = 0; t < 8; t++) {
                    mma_bf16(oacc[half * 8 + t], ah, bv[t]);
                    mma_bf16(oacc[half * 8 + t], alr, bv[t]);
                }
                #pragma unroll
                for (int g = 0; g < 4; g++) {
                    uint32_t r0, r1, r2, r3;
                    ldsm_x4_t(r0, r1, r2, r3,
                              sb + SM_VL + vrow + (uint32_t)(half * 128 + g * 32));
                    bv[2 * g][0] = r0; bv[2 * g][1] = r1;
                    bv[2 * g + 1][0] = r2; bv[2 * g + 1][1] = r3;
                }
                #pragma unroll
                for (int t = 0; t < 8; t++)
                    mma_bf16(oacc[half * 8 + t], ah, bv[t]);
            }
        }

        __syncthreads();
        if (has_next) load_v(kt + 64);
        CP_COMMIT();
    }

    const float inv0 = 1.f / l0, inv1 = 1.f / l1;
    const int gr = lane >> 2, gc = (lane & 3) * 2;
    const int row0 = b * S_ + q0 + wr + gr;
    #pragma unroll
    for (int nt = 0; nt < 16; nt++) {
        const int col = h * DV + nt * 8 + gc;
        __nv_bfloat162 hi, lo;
        hl_split2(oacc[nt][0] * inv0, oacc[nt][1] * inv0, hi, lo);
        *(__nv_bfloat162*)(ohi + (size_t)row0 * (NH_ * DV) + col) = hi;
        *(__nv_bfloat162*)(olo + (size_t)row0 * (NH_ * DV) + col) = lo;
        hl_split2(oacc[nt][2] * inv1, oacc[nt][3] * inv1, hi, lo);
        *(__nv_bfloat162*)(ohi + (size_t)(row0 + 8) * (NH_ * DV) + col) = hi;
        *(__nv_bfloat162*)(olo + (size_t)(row0 + 8) * (NH_ * DV) + col) = lo;
    }
}

// ---------------------------------------------------------------------------
// Launcher
// ---------------------------------------------------------------------------
static inline void run_conv(const float* in, __nv_bfloat16* hi, __nv_bfloat16* lo,
                            int R, int Rpad, int Kin, int ldin)
{
    const int total = Rpad * (Kin / 4);
    conv_hl_kernel<<<(total + 255) / 256, 256>>>(in, hi, lo, R, Rpad, Kin, ldin);
}

extern "C" void kernel_launch(void* const* d_in, const int* in_sizes, int n_in,
                              void* d_out, int out_size)
{
    const float* hs    = (const float*)d_in[0];
    const float* wq_a  = (const float*)d_in[1];
    const float* qnw   = (const float*)d_in[2];
    const float* wq_b  = (const float*)d_in[3];
    const float* wkv_a = (const float*)d_in[4];
    const float* kvnw  = (const float*)d_in[5];
    const float* wkv_b = (const float*)d_in[6];
    const float* wo    = (const float*)d_in[7];
    float* out = (float*)d_out;

    void* p;
    cudaGetSymbolAddress(&p, g_qlora); float* qlora = (float*)p;
    cudaGetSymbolAddress(&p, g_kv);    float* kvbuf = (float*)p;
    cudaGetSymbolAddress(&p, g_a3);    __nv_bfloat16* a3 = (__nv_bfloat16*)p;
    cudaGetSymbolAddress(&p, g_b3);    __nv_bfloat16* b3 = (__nv_bfloat16*)p;
    cudaGetSymbolAddress(&p, g_qh);    __nv_bfloat16* qh = (__nv_bfloat16*)p;
    cudaGetSymbolAddress(&p, g_ql2);   __nv_bfloat16* ql = (__nv_bfloat16*)p;
    cudaGetSymbolAddress(&p, g_kh);    __nv_bfloat16* kh = (__nv_bfloat16*)p;
    cudaGetSymbolAddress(&p, g_kl);    __nv_bfloat16* kl = (__nv_bfloat16*)p;
    cudaGetSymbolAddress(&p, g_kpeh);  __nv_bfloat16* kpeh = (__nv_bfloat16*)p;
    cudaGetSymbolAddress(&p, g_kpel);  __nv_bfloat16* kpel = (__nv_bfloat16*)p;
    cudaGetSymbolAddress(&p, g_vrh);   __nv_bfloat16* vrh = (__nv_bfloat16*)p;
    cudaGetSymbolAddress(&p, g_vrl);   __nv_bfloat16* vrl = (__nv_bfloat16*)p;

    cudaFuncSetAttribute(flash_mma_kernel, cudaFuncAttributeMaxDynamicSharedMemorySize,
                         FLASH_SMEM);

    freq_init_kernel<<<1, 32>>>();

    // 1) q_lora = hs @ wq_a^T        [4096, 1536], K=2048
    run_conv(hs, a3, a3 + (size_t)BS * H_, BS, BS, H_, H_);
    run_conv(wq_a, b3, b3 + (size_t)QL * H_, QL, QL, H_, H_);
    gemm_bf16_kernel<<<dim3(QL / 64, BS / 128), 128>>>(
        a3, a3 + (size_t)BS * H_, b3, b3 + (size_t)QL * H_,
        qlora, nullptr, nullptr, QL, H_, QL, 0);

    // 2) kv = hs @ wkv_a^T  [4096, 576] (Npad 640): fp32 kv_c + rope'd pe -> compact kpe
    run_conv(wkv_a, b3, b3 + (size_t)640 * H_, KVL + DR, 640, H_, H_);
    gemm_kv_kernel<<<dim3(640 / 64, BS / 128), 128>>>(
        a3, a3 + (size_t)BS * H_, b3, b3 + (size_t)640 * H_,
        kvbuf, kpeh, kpel, KVL + DR, H_, KVL + DR);

    // 3) q = q_lora @ wq_b^T         [4096, 3072], K=1536; fused rope + hi/lo out
    rms_conv_hl_kernel<<<BS, 256>>>(qlora, qnw, a3, a3 + (size_t)BS * QL, QL, QL);
    run_conv(wq_b, b3, b3 + (size_t)3072 * QL, NH_ * DQK, NH_ * DQK, QL, QL);
    gemm_bf16_kernel<<<dim3((NH_ * DQK) / 64, BS / 128), 128>>>(
        a3, a3 + (size_t)BS * QL, b3, b3 + (size_t)3072 * QL,
        nullptr, qh, ql, NH_ * DQK, QL, NH_ * DQK, 1);

    // 4) kv_x = kv_c @ wkv_b^T       [4096, 4096], K=512: k-nope + V row-major hi/lo
    rms_conv_hl_kernel<<<BS, 256>>>(kvbuf, kvnw, a3, a3 + (size_t)BS * KVL, KVL, KVL + DR);
    run_conv(wkv_b, b3, b3 + (size_t)4096 * KVL, NH_ * (DN + DV), NH_ * (DN + DV), KVL, KVL);
    gemm_kvx_kernel<<<dim3((NH_ * (DN + DV)) / 64, BS / 128), 128>>>(
        a3, a3 + (size_t)BS * KVL, b3, b3 + (size_t)4096 * KVL,
        kh, kl, vrh, vrl, KVL);

    // 5) flash attention (V row-major via ldmatrix.trans) -> a3 hi/lo
    flash_mma_kernel<<<dim3(S_ / 128, NH_, B_), 256, FLASH_SMEM>>>(
        qh, ql, kh, kl, kpeh, kpel, vrh, vrl, a3, a3 + (size_t)BS * (NH_ * DV));

    // 6) out = attn @ wo^T           [4096, 2048], K=2048
    run_conv(wo, b3, b3 + (size_t)H_ * (NH_ * DV), H_, H_, NH_ * DV, NH_ * DV);
    gemm_bf16_kernel<<<dim3(H_ / 64, BS / 128), 128>>>(
        a3, a3 + (size_t)BS * (NH_ * DV), b3, b3 + (size_t)H_ * (NH_ * DV),
        out, nullptr, nullptr, H_, NH_ * DV, H_, 0);
}